// round 11
// baseline (speedup 1.0000x reference)
#include <cuda_runtime.h>
#include <cuda_fp16.h>
#include <cstdint>

// GCN — reassociated 3-layer GCN, fp16-split mma.sync, globally scaled.
// x' = x/64; out *= 64.
// G1: t1=Aw_h@x_h (1p, wide)    G2: h1=relu(t1@(W1h+W1l)) (2p)
// G3: t2=Aw_h@h1_h (1p, wide)   G4: h2=relu(t2@W2_h) (1p, wide)
// G5: s3=h2@(W3h+W3l) (2p)      G6: out=64*Aw_h@s3_h (1p, wide)

#define NN 4096
#define BB 4
#define XSCALE (1.0f / 64.0f)
#define OSCALE 64.0f

__device__ uint4 g_AwH[(size_t)NN * NN / 8];
__device__ uint4 g_FaH[(size_t)BB * NN * 1024 / 8];  // ping
__device__ uint4 g_FbH[(size_t)BB * NN * 1024 / 8];  // pong
__device__ uint4 g_WH[114688];  // W1@0, W2@16384, W3@81920
__device__ uint4 g_WL[114688];

// ---------------------------------------------------------------------------
__device__ __forceinline__ uint32_t smem_u32(const void* p) {
    uint32_t a;
    asm("{ .reg .u64 t; cvta.to.shared.u64 t, %1; cvt.u32.u64 %0, t; }"
        : "=r"(a) : "l"(p));
    return a;
}
__device__ __forceinline__ uint32_t pk(float a, float b) {
    __half2 t = __floats2half2_rn(a, b);
    return *reinterpret_cast<uint32_t*>(&t);
}
__device__ __forceinline__ void split2(float v, float& h, float& l) {
    h = __half2float(__float2half_rn(v));
    l = v - h;
}
__device__ __forceinline__ void cpa16(uint32_t saddr, const void* gaddr) {
    asm volatile("cp.async.cg.shared.global [%0], [%1], 16;"
                 :: "r"(saddr), "l"(gaddr));
}
#define CP_COMMIT() asm volatile("cp.async.commit_group;" ::: "memory")
#define CP_WAIT1()  asm volatile("cp.async.wait_group 1;" ::: "memory")
#define CP_WAIT0()  asm volatile("cp.async.wait_group 0;" ::: "memory")

__device__ __forceinline__ void mma16816(float* c, const uint4& a,
                                         uint32_t b0, uint32_t b1) {
    asm volatile(
        "mma.sync.aligned.m16n8k16.row.col.f32.f16.f16.f32 "
        "{%0,%1,%2,%3},{%4,%5,%6,%7},{%8,%9},{%0,%1,%2,%3};"
        : "+f"(c[0]), "+f"(c[1]), "+f"(c[2]), "+f"(c[3])
        : "r"(a.x), "r"(a.y), "r"(a.z), "r"(a.w), "r"(b0), "r"(b1));
}

// ---------------------------------------------------------------------------
// prep_A_tile: Aw = adj .* S -> A-frag hi only.
// ---------------------------------------------------------------------------
__global__ __launch_bounds__(256)
void prep_A_tile(const float* __restrict__ src, const float* __restrict__ mul,
                 uint4* __restrict__ dhi, int M, int K) {
    __shared__ float smt[128][68];
    const int tid = threadIdx.x;
    const int kcb = blockIdx.x;
    const size_t mb = blockIdx.y;
    const int colBase = kcb * 64;
    const size_t rowBase = mb * 128;

    const int c4 = tid & 15;
    const int r0 = tid >> 4;
#pragma unroll
    for (int i = 0; i < 8; i++) {
        int r = r0 + i * 16;
        const float4 v = ((const float4*)(src + (rowBase + r) * K + colBase))[c4];
        const float4 s = ((const float4*)(mul + (rowBase + r) * K + colBase))[c4];
        float4 o = make_float4(v.x * s.x, v.y * s.y, v.z * s.z, v.w * s.w);
        *(float4*)&smt[r][c4 * 4] = o;
    }
    __syncthreads();

    const int lane = tid & 31;
    const int mt = tid >> 5;
    const int rr = mt * 16 + (lane >> 2);
    const int cb = (lane & 3) * 2;
    const int nkc = K >> 4;
#pragma unroll
    for (int kb = 0; kb < 4; kb++) {
        int c0 = kb * 16 + cb;
        uint4 H = make_uint4(
            pk(smt[rr][c0],     smt[rr][c0 + 1]),
            pk(smt[rr + 8][c0], smt[rr + 8][c0 + 1]),
            pk(smt[rr][c0 + 8], smt[rr][c0 + 9]),
            pk(smt[rr + 8][c0 + 8], smt[rr + 8][c0 + 9]));
        dhi[(mb * nkc + (size_t)(kcb * 4 + kb)) * 256 + tid] = H;
    }
}

// ---------------------------------------------------------------------------
// prep_B_tile: src [K,Ncols] f32 * scale -> B-frag hi (+lo).
// grid: (Ncols/128, K/32, batch), 256 threads.
// ---------------------------------------------------------------------------
__global__ __launch_bounds__(256)
void prep_B_tile(const float* __restrict__ src, uint4* __restrict__ dhi,
                 uint4* __restrict__ dlo, int K, int Ncols,
                 size_t sSrc, size_t sDst, float scale) {
    __shared__ float smt[32][132];
    src += (size_t)blockIdx.z * sSrc;
    dhi += (size_t)blockIdx.z * sDst;
    if (dlo) dlo += (size_t)blockIdx.z * sDst;
    const int tid = threadIdx.x;
    const int nb = blockIdx.x;
    const int kcb = blockIdx.y;

    const int c4 = tid & 31;
    const int r0 = tid >> 5;
#pragma unroll
    for (int i = 0; i < 4; i++) {
        int r = r0 + i * 8;
        float4 v = ((const float4*)(src + (size_t)(kcb * 32 + r) * Ncols +
                                    nb * 128))[c4];
        v.x *= scale; v.y *= scale; v.z *= scale; v.w *= scale;
        *(float4*)&smt[r][c4 * 4] = v;
    }
    __syncthreads();

    const int lane = tid & 31;
    const int j = tid >> 5;
    const int n0 = j * 16 + (lane >> 2);
    const int k0b = (lane & 3) * 2;
    const int nnb = Ncols >> 7;
#pragma unroll
    for (int kk = 0; kk < 2; kk++) {
        int k0 = kk * 16 + k0b;
        float e[8];
        e[0] = smt[k0][n0];     e[1] = smt[k0 + 1][n0];
        e[2] = smt[k0 + 8][n0]; e[3] = smt[k0 + 9][n0];
        e[4] = smt[k0][n0 + 8];     e[5] = smt[k0 + 1][n0 + 8];
        e[6] = smt[k0 + 8][n0 + 8]; e[7] = smt[k0 + 9][n0 + 8];
        float h[8], l[8];
#pragma unroll
        for (int r = 0; r < 8; r++) split2(e[r], h[r], l[r]);
        size_t blk = (size_t)(kcb * 2 + kk) * nnb + nb;
        dhi[blk * 256 + tid] = make_uint4(pk(h[0], h[1]), pk(h[2], h[3]),
                                          pk(h[4], h[5]), pk(h[6], h[7]));
        if (dlo)
            dlo[blk * 256 + tid] = make_uint4(pk(l[0], l[1]), pk(l[2], l[3]),
                                              pk(l[4], l[5]), pk(l[6], l[7]));
    }
}

// ---------------------------------------------------------------------------
// Wide 1-product GEMM: BM=128, BN=256, BK=32, 512 threads (16 warps 2m x 8n,
// warp tile 64x32), 3-stage cp.async (24KB/stage). Batches folded into N.
// MODE 0: fp32 store (scaled). MODE 1: emit A-frags (hi). RELU optional.
// grid: x = global 256-col blocks, y = row blocks (within batch for Aw GEMMs).
// ---------------------------------------------------------------------------
template <int MODE, int RELU>
__global__ __launch_bounds__(512, 1)
void gemm_wide(const uint4* __restrict__ Ah, const uint4* __restrict__ Bh,
               float* __restrict__ C, uint4* __restrict__ FH,
               int K, int nnbL, size_t sBu4, size_t sCf,
               int mbPerBatch, int nkNext, float outScale) {
    extern __shared__ __align__(128) char sm[];
    const int tid = threadIdx.x;
    const int lane = tid & 31;
    const int wid = tid >> 5;
    const int wm = wid >> 3;      // 0..1
    const int wn = wid & 7;       // 0..7
    const int wnq = wn & 3;
    const int q = wn >> 2;        // which 128-col block of this CTA
    const int bx = blockIdx.x;
    const int by = blockIdx.y;

    const int nc2 = K >> 5;
    const int nkc = K >> 4;
    const uint32_t sbase = smem_u32(sm);

    float acc[4][4][4];
#pragma unroll
    for (int i = 0; i < 4; i++)
#pragma unroll
        for (int j = 0; j < 4; j++)
#pragma unroll
            for (int r = 0; r < 4; r++) acc[i][j][r] = 0.f;

    // B addressing: global n-block g for load slot u; smem offset = 8192+u*16
    auto bsrc = [&](int u, int c) -> const uint4* {
        int bb = u >> 8;              // 0..3 : [q][kk]
        int qq = bb >> 1, kk = bb & 1;
        int g = bx * 2 + qq;
        int bt = g / nnbL;
        int loc = g - bt * nnbL;
        return Bh + (size_t)bt * sBu4 +
               ((size_t)((c * 2 + kk) * nnbL + loc)) * 256 + (u & 255);
    };
    auto issue = [&](int s, int c) {
        uint32_t ss = sbase + s * 24576;
        size_t ab = ((size_t)by * nkc + (size_t)(c << 1) + (tid >> 8)) * 256 +
                    (tid & 255);
        cpa16(ss + tid * 16, Ah + ab);
        cpa16(ss + 8192 + tid * 16, bsrc(tid, c));
        cpa16(ss + 8192 + (tid + 512) * 16, bsrc(tid + 512, c));
    };

    issue(0, 0); CP_COMMIT();
    issue(1, 1); CP_COMMIT();

    for (int c = 0; c < nc2; ++c) {
        int s = c % 3;
        CP_WAIT1();
        __syncthreads();
        const char* st = sm + s * 24576;
#pragma unroll
        for (int kk = 0; kk < 2; ++kk) {
            const uint4* sA = (const uint4*)(st + kk * 4096);
            const uint4* sB = (const uint4*)(st + 8192 + (q * 2 + kk) * 4096);
            uint4 fAh[4], fBh[2];
#pragma unroll
            for (int i = 0; i < 4; i++)
                fAh[i] = sA[(wm * 4 + i) * 32 + lane];
#pragma unroll
            for (int q2 = 0; q2 < 2; q2++)
                fBh[q2] = sB[(wnq * 2 + q2) * 32 + lane];
#pragma unroll
            for (int i = 0; i < 4; i++) {
#pragma unroll
                for (int j = 0; j < 4; j++) {
                    int p = j >> 1;
                    uint32_t b0 = (j & 1) ? fBh[p].z : fBh[p].x;
                    uint32_t b1 = (j & 1) ? fBh[p].w : fBh[p].y;
                    mma16816(acc[i][j], fAh[i], b0, b1);
                }
            }
        }
        if (c + 2 < nc2) issue((c + 2) % 3, c + 2);
        CP_COMMIT();
    }

    if (RELU) {
#pragma unroll
        for (int i = 0; i < 4; i++)
#pragma unroll
            for (int j = 0; j < 4; j++)
#pragma unroll
                for (int r = 0; r < 4; r++) acc[i][j][r] = fmaxf(acc[i][j][r], 0.f);
    }

    const int g = bx * 2 + q;
    const int bt = g / nnbL;
    const int loc = g - bt * nnbL;

    if (MODE == 0) {
        float* Cb = C + (size_t)bt * sCf;
        const int NcolsL = nnbL << 7;
        const int row0 = by * 128 + wm * 64 + (lane >> 2);
        const int colb = loc * 128 + wnq * 32 + (lane & 3) * 2;
#pragma unroll
        for (int i = 0; i < 4; i++)
#pragma unroll
            for (int j = 0; j < 4; j++) {
                int r = row0 + i * 16;
                int col = colb + j * 8;
                *reinterpret_cast<float2*>(Cb + (size_t)r * NcolsL + col) =
                    make_float2(acc[i][j][0] * outScale, acc[i][j][1] * outScale);
                *reinterpret_cast<float2*>(Cb + (size_t)(r + 8) * NcolsL + col) =
                    make_float2(acc[i][j][2] * outScale, acc[i][j][3] * outScale);
            }
    } else {
        const size_t mb = (size_t)bt * mbPerBatch + by;
#pragma unroll
        for (int i = 0; i < 4; i++)
#pragma unroll
            for (int jp = 0; jp < 2; jp++) {
                float* a0 = acc[i][2 * jp];
                float* a1 = acc[i][2 * jp + 1];
                int kcg = loc * 8 + wnq * 2 + jp;
                size_t di = (mb * nkNext + kcg) * 256 + (wm * 4 + i) * 32 + lane;
                FH[di] = make_uint4(pk(a0[0], a0[1]), pk(a0[2], a0[3]),
                                    pk(a1[0], a1[1]), pk(a1[2], a1[3]));
            }
    }
}

// ---------------------------------------------------------------------------
// Narrow 2-product GEMM (unchanged core): BM=128, BN=128, 256 thr, MODE 2
// (B-frag emission via smem transpose). A hi-only, B hi+lo.
// ---------------------------------------------------------------------------
template <int RELU>
__global__ __launch_bounds__(256, 2)
void gemm_bfrag(const uint4* __restrict__ Ah, const uint4* __restrict__ Bh,
                const uint4* __restrict__ Bl, uint4* __restrict__ FH,
                int Ncols, int K, int nbX, size_t sFu4) {
    extern __shared__ __align__(128) char sm[];
    const int tid = threadIdx.x;
    const int lane = tid & 31;
    const int wid = tid >> 5;
    const int wm = wid >> 2;
    const int wn = wid & 3;
    const int bx = blockIdx.x % nbX;
    const int by = blockIdx.y;

    const int nc2 = K >> 5;
    const int nkc = K >> 4;
    const int nnb = Ncols >> 7;
    const uint32_t sbase = smem_u32(sm);

    float acc[4][4][4];
#pragma unroll
    for (int i = 0; i < 4; i++)
#pragma unroll
        for (int j = 0; j < 4; j++)
#pragma unroll
            for (int r = 0; r < 4; r++) acc[i][j][r] = 0.f;

    auto issue = [&](int s, int c) {
        uint32_t sa = sbase + s * 24576 + tid * 16;
        size_t ab = ((size_t)by * nkc + (size_t)(c << 1)) * 256 + tid;
        size_t bb0 = ((size_t)(c << 1) * nnb + bx) * 256 + tid;
        size_t bb1 = bb0 + (size_t)nnb * 256;
        cpa16(sa,         Ah + ab);
        cpa16(sa + 4096,  Ah + ab + 256);
        cpa16(sa + 8192,  Bh + bb0);
        cpa16(sa + 12288, Bh + bb1);
        cpa16(sa + 16384, Bl + bb0);
        cpa16(sa + 20480, Bl + bb1);
    };

    issue(0, 0); CP_COMMIT();
    issue(1, 1); CP_COMMIT();

    for (int c = 0; c < nc2; ++c) {
        int s = c % 3;
        CP_WAIT1();
        __syncthreads();
        const char* st = sm + s * 24576;
#pragma unroll
        for (int kk = 0; kk < 2; ++kk) {
            const uint4* sAh = (const uint4*)(st + kk * 4096);
            const uint4* sBh = (const uint4*)(st + 8192 + kk * 4096);
            const uint4* sBl = (const uint4*)(st + 16384 + kk * 4096);
            uint4 fAh[4], fBh[2], fBl[2];
#pragma unroll
            for (int i = 0; i < 4; i++)
                fAh[i] = sAh[(wm * 4 + i) * 32 + lane];
#pragma unroll
            for (int p = 0; p < 2; p++) {
                fBh[p] = sBh[(wn * 2 + p) * 32 + lane];
                fBl[p] = sBl[(wn * 2 + p) * 32 + lane];
            }
#pragma unroll
            for (int i = 0; i < 4; i++) {
#pragma unroll
                for (int j = 0; j < 4; j++) {
                    int p = j >> 1;
                    uint32_t bh0 = (j & 1) ? fBh[p].z : fBh[p].x;
                    uint32_t bh1 = (j & 1) ? fBh[p].w : fBh[p].y;
                    uint32_t bl0 = (j & 1) ? fBl[p].z : fBl[p].x;
                    uint32_t bl1 = (j & 1) ? fBl[p].w : fBl[p].y;
                    mma16816(acc[i][j], fAh[i], bh0, bh1);
                    mma16816(acc[i][j], fAh[i], bl0, bl1);
                }
            }
        }
        if (c + 2 < nc2) issue((c + 2) % 3, c + 2);
        CP_COMMIT();
    }

    if (RELU) {
#pragma unroll
        for (int i = 0; i < 4; i++)
#pragma unroll
            for (int j = 0; j < 4; j++)
#pragma unroll
                for (int r = 0; r < 4; r++) acc[i][j][r] = fmaxf(acc[i][j][r], 0.f);
    }

    // emit B-frags (hi) via smem transpose
    CP_WAIT0();
    __syncthreads();
    float* sf = (float*)sm;  // 128 x 132 fp32
    const int r0 = wm * 64 + (lane >> 2);
    const int c0 = wn * 32 + (lane & 3) * 2;
#pragma unroll
    for (int i = 0; i < 4; i++)
#pragma unroll
        for (int j = 0; j < 4; j++) {
            int rr = r0 + i * 16, cc = c0 + j * 8;
            sf[rr * 132 + cc] = acc[i][j][0];
            sf[rr * 132 + cc + 1] = acc[i][j][1];
            sf[(rr + 8) * 132 + cc] = acc[i][j][2];
            sf[(rr + 8) * 132 + cc + 1] = acc[i][j][3];
        }
    __syncthreads();
    const int batchO = by >> 5;
    const int mbLoc = by & 31;
    const int jj = tid >> 5;
    const int ln = tid & 31;
    const int n0 = 16 * jj + (ln >> 2);
    const int k0b = (ln & 3) * 2;
#pragma unroll
    for (int kb = 0; kb < 8; kb++) {
        int k0 = kb * 16 + k0b;
        float e[8];
        e[0] = sf[k0 * 132 + n0];
        e[1] = sf[(k0 + 1) * 132 + n0];
        e[2] = sf[(k0 + 8) * 132 + n0];
        e[3] = sf[(k0 + 9) * 132 + n0];
        e[4] = sf[k0 * 132 + n0 + 8];
        e[5] = sf[(k0 + 1) * 132 + n0 + 8];
        e[6] = sf[(k0 + 8) * 132 + n0 + 8];
        e[7] = sf[(k0 + 9) * 132 + n0 + 8];
        int kc = mbLoc * 8 + kb;
        size_t di = (size_t)batchO * sFu4 + ((size_t)kc * nbX + bx) * 256 + tid;
        FH[di] = make_uint4(pk(e[0], e[1]), pk(e[2], e[3]),
                            pk(e[4], e[5]), pk(e[6], e[7]));
    }
}

// ---------------------------------------------------------------------------
template <int MODE, int RELU>
static void launch_wide(int gx, int gy, int K, const uint4* A, const uint4* B,
                        float* C, uint4* FH, int nnbL, size_t sBu4, size_t sCf,
                        int mbPerBatch, int nkNext, float outScale) {
    int smem = 3 * 24576;
    cudaFuncSetAttribute(gemm_wide<MODE, RELU>,
                         cudaFuncAttributeMaxDynamicSharedMemorySize, smem);
    gemm_wide<MODE, RELU><<<dim3(gx, gy), 512, smem>>>(
        A, B, C, FH, K, nnbL, sBu4, sCf, mbPerBatch, nkNext, outScale);
}

template <int RELU>
static void launch_bfrag(int M, int Ncols, int K, const uint4* Ah,
                         const uint4* Bh, const uint4* Bl, uint4* FH,
                         size_t sFu4) {
    int nbX = Ncols / 128;
    int smem = 3 * 24576;
    // MODE2 epilogue needs 128x132 fp32 = 67584 B <= 73728 OK
    cudaFuncSetAttribute(gemm_bfrag<RELU>,
                         cudaFuncAttributeMaxDynamicSharedMemorySize, smem);
    gemm_bfrag<RELU><<<dim3(nbX, M / 128), 256, smem>>>(Ah, Bh, Bl, FH, Ncols,
                                                        K, nbX, sFu4);
}

extern "C" void kernel_launch(void* const* d_in, const int* in_sizes, int n_in,
                              void* d_out, int out_size) {
    const float* x   = (const float*)d_in[0];  // [B, N, 256]
    const float* adj = (const float*)d_in[1];
    const float* S   = (const float*)d_in[2];
    const float* W1  = (const float*)d_in[3];  // [256, 512]
    const float* W2  = (const float*)d_in[4];  // [512, 1024]
    const float* W3  = (const float*)d_in[5];  // [1024, 256]
    float* out = (float*)d_out;                // [B, N, 256]

    uint4 *AwH, *FaH, *FbH, *WH, *WL;
    cudaGetSymbolAddress((void**)&AwH, g_AwH);
    cudaGetSymbolAddress((void**)&FaH, g_FaH);
    cudaGetSymbolAddress((void**)&FbH, g_FbH);
    cudaGetSymbolAddress((void**)&WH, g_WH);
    cudaGetSymbolAddress((void**)&WL, g_WL);

    const size_t sX  = (size_t)NN * 256 / 8;   // per-batch u4 strides
    const size_t sH1 = (size_t)NN * 512 / 8;
    const size_t sS3 = (size_t)NN * 256 / 8;

    // One-time preps
    prep_A_tile<<<dim3(NN / 64, NN / 128), 256>>>(adj, S, AwH, NN, NN);
    prep_B_tile<<<dim3(2, NN / 32, BB), 256>>>(x, FbH, nullptr, NN, 256,
                                               (size_t)NN * 256, sX, XSCALE);
    prep_B_tile<<<dim3(4, 8, 1), 256>>>(W1, WH, WL, 256, 512, 0, 0, 1.0f);
    prep_B_tile<<<dim3(8, 16, 1), 256>>>(W2, WH + 16384, nullptr, 512, 1024,
                                         0, 0, 1.0f);
    prep_B_tile<<<dim3(2, 32, 1), 256>>>(W3, WH + 81920, WL + 81920, 1024, 256,
                                         0, 0, 1.0f);

    // G1: t1 = Aw_h @ x_h -> A-frags (Fa). wide, global N = 1024.
    launch_wide<1, 0>(4, 32, NN, AwH, FbH, nullptr, FaH,
                      /*nnbL=*/2, sX, 0, /*mbPerBatch=*/32, /*nkNext=*/16, 1.0f);
    // G2: h1 = relu(t1 @ (W1h+W1l)) -> B-frags (Fb). 2-product narrow.
    launch_bfrag<1>(BB * NN, 512, 256, FaH, WH, WL, FbH, sH1);
    // G3: t2 = Aw_h @ h1_h -> A-frags (Fa). wide, global N = 2048.
    launch_wide<1, 0>(8, 32, NN, AwH, FbH, nullptr, FaH,
                      /*nnbL=*/4, sH1, 0, 32, /*nkNext=*/32, 1.0f);
    // G4: h2 = relu(t2_h @ W2_h) -> A-frags (Fb). wide, N = 1024 single batch.
    launch_wide<1, 1>(4, (BB * NN) / 128, 512, FaH, WH + 16384, nullptr, FbH,
                      /*nnbL=*/8, 0, 0, /*mbPerBatch=*/BB * NN / 128,
                      /*nkNext=*/64, 1.0f);
    // G5: s3 = h2_h @ (W3h+W3l) -> B-frags (Fa). 2-product narrow.
    launch_bfrag<0>(BB * NN, 256, 1024, FbH, WH + 81920, WL + 81920, FaH, sS3);
    // G6: out = 64 * (Aw_h @ s3_h) -> fp32. wide, global N = 1024.
    launch_wide<0, 0>(4, 32, NN, AwH, FaH, out, nullptr,
                      /*nnbL=*/2, sS3, (size_t)NN * 256, 32, 0, OSCALE);
}

// round 12
// speedup vs baseline: 1.3721x; 1.3721x over previous
#include <cuda_runtime.h>
#include <cuda_fp16.h>
#include <cstdint>

// GCN — reassociated 3-layer GCN, fp16 hi-only mma.sync, globally scaled.
// x' = x/64; out *= 64 (relu positively homogeneous).
// G1: t1=Aw@x (1p)   G2: h1=relu(t1@W1) (1p)   G3: t2=Aw@h1 (1p)
// G4: h2=relu(t2@W2) (1p)   G5: s3=h2@W3 (1p)   G6: out=64*Aw@s3 (1p)
// All operands fp16 hi parts; accumulation fp32. Calibrated rel_err ~3.2e-4.

#define NN 4096
#define BB 4
#define XSCALE (1.0f / 64.0f)
#define OSCALE 64.0f

// Fragment-tiled storage: A blocks 128m x 16k = 256 uint4 (block = mb*nkc+kc),
// B blocks 16k x 128n = 256 uint4 (block = kc*nnb+nb).
__device__ uint4 g_AwH[(size_t)NN * NN / 8];
__device__ uint4 g_FaH[(size_t)BB * NN * 1024 / 8];  // ping
__device__ uint4 g_FbH[(size_t)BB * NN * 1024 / 8];  // pong
__device__ uint4 g_WH[114688];  // W1@0, W2@16384, W3@81920

// ---------------------------------------------------------------------------
__device__ __forceinline__ uint32_t smem_u32(const void* p) {
    uint32_t a;
    asm("{ .reg .u64 t; cvta.to.shared.u64 t, %1; cvt.u32.u64 %0, t; }"
        : "=r"(a) : "l"(p));
    return a;
}
__device__ __forceinline__ uint32_t pk(float a, float b) {
    __half2 t = __floats2half2_rn(a, b);
    return *reinterpret_cast<uint32_t*>(&t);
}
__device__ __forceinline__ void cpa16(uint32_t saddr, const void* gaddr) {
    asm volatile("cp.async.cg.shared.global [%0], [%1], 16;"
                 :: "r"(saddr), "l"(gaddr));
}
#define CP_COMMIT() asm volatile("cp.async.commit_group;" ::: "memory")
#define CP_WAIT1()  asm volatile("cp.async.wait_group 1;" ::: "memory")
#define CP_WAIT0()  asm volatile("cp.async.wait_group 0;" ::: "memory")

__device__ __forceinline__ void mma16816(float* c, const uint4& a,
                                         uint32_t b0, uint32_t b1) {
    asm volatile(
        "mma.sync.aligned.m16n8k16.row.col.f32.f16.f16.f32 "
        "{%0,%1,%2,%3},{%4,%5,%6,%7},{%8,%9},{%0,%1,%2,%3};"
        : "+f"(c[0]), "+f"(c[1]), "+f"(c[2]), "+f"(c[3])
        : "r"(a.x), "r"(a.y), "r"(a.z), "r"(a.w), "r"(b0), "r"(b1));
}

// ---------------------------------------------------------------------------
// prep_A_tile: Aw = adj .* S -> A-frag hi only. Coalesced 128x64 tile stage.
// grid: (K/64, M/128), 256 threads.
// ---------------------------------------------------------------------------
__global__ __launch_bounds__(256)
void prep_A_tile(const float* __restrict__ src, const float* __restrict__ mul,
                 uint4* __restrict__ dhi, int M, int K) {
    __shared__ float smt[128][68];
    const int tid = threadIdx.x;
    const int kcb = blockIdx.x;
    const size_t mb = blockIdx.y;
    const int colBase = kcb * 64;
    const size_t rowBase = mb * 128;

    const int c4 = tid & 15;
    const int r0 = tid >> 4;
#pragma unroll
    for (int i = 0; i < 8; i++) {
        int r = r0 + i * 16;
        const float4 v = ((const float4*)(src + (rowBase + r) * K + colBase))[c4];
        const float4 s = ((const float4*)(mul + (rowBase + r) * K + colBase))[c4];
        float4 o = make_float4(v.x * s.x, v.y * s.y, v.z * s.z, v.w * s.w);
        *(float4*)&smt[r][c4 * 4] = o;
    }
    __syncthreads();

    const int lane = tid & 31;
    const int mt = tid >> 5;
    const int rr = mt * 16 + (lane >> 2);
    const int cb = (lane & 3) * 2;
    const int nkc = K >> 4;
#pragma unroll
    for (int kb = 0; kb < 4; kb++) {
        int c0 = kb * 16 + cb;
        uint4 H = make_uint4(
            pk(smt[rr][c0],     smt[rr][c0 + 1]),
            pk(smt[rr + 8][c0], smt[rr + 8][c0 + 1]),
            pk(smt[rr][c0 + 8], smt[rr][c0 + 9]),
            pk(smt[rr + 8][c0 + 8], smt[rr + 8][c0 + 9]));
        dhi[(mb * nkc + (size_t)(kcb * 4 + kb)) * 256 + tid] = H;
    }
}

// ---------------------------------------------------------------------------
// prep_B_tile: src [K,Ncols] f32 * scale -> B-frag hi only. Coalesced
// 32x128 tile stage. grid: (Ncols/128, K/32, batch), 256 threads.
// ---------------------------------------------------------------------------
__global__ __launch_bounds__(256)
void prep_B_tile(const float* __restrict__ src, uint4* __restrict__ dhi,
                 int K, int Ncols, size_t sSrc, size_t sDst, float scale) {
    __shared__ float smt[32][132];
    src += (size_t)blockIdx.z * sSrc;
    dhi += (size_t)blockIdx.z * sDst;
    const int tid = threadIdx.x;
    const int nb = blockIdx.x;
    const int kcb = blockIdx.y;

    const int c4 = tid & 31;
    const int r0 = tid >> 5;
#pragma unroll
    for (int i = 0; i < 4; i++) {
        int r = r0 + i * 8;
        float4 v = ((const float4*)(src + (size_t)(kcb * 32 + r) * Ncols +
                                    nb * 128))[c4];
        v.x *= scale; v.y *= scale; v.z *= scale; v.w *= scale;
        *(float4*)&smt[r][c4 * 4] = v;
    }
    __syncthreads();

    const int lane = tid & 31;
    const int j = tid >> 5;
    const int n0 = j * 16 + (lane >> 2);
    const int k0b = (lane & 3) * 2;
    const int nnb = Ncols >> 7;
#pragma unroll
    for (int kk = 0; kk < 2; kk++) {
        int k0 = kk * 16 + k0b;
        float e[8];
        e[0] = smt[k0][n0];     e[1] = smt[k0 + 1][n0];
        e[2] = smt[k0 + 8][n0]; e[3] = smt[k0 + 9][n0];
        e[4] = smt[k0][n0 + 8];     e[5] = smt[k0 + 1][n0 + 8];
        e[6] = smt[k0 + 8][n0 + 8]; e[7] = smt[k0 + 9][n0 + 8];
        size_t blk = (size_t)(kcb * 2 + kk) * nnb + nb;
        dhi[blk * 256 + tid] = make_uint4(pk(e[0], e[1]), pk(e[2], e[3]),
                                          pk(e[4], e[5]), pk(e[6], e[7]));
    }
}

// ---------------------------------------------------------------------------
// GEMM: BM=128, BN=128, BK=32, 3-stage cp.async (16KB/stage), 8 warps (2x4),
// warp tile 64x32, 1 product (A-hi x B-hi).
// MODE 0: fp32 store (scaled).  MODE 1: emit A-frags (hi).
// MODE 2: emit B-frags (hi, smem transpose).  RELU before emission.
// grid: x = nbX*batch (bx = x%nbX, bz = x/nbX), y = M/128.
// ---------------------------------------------------------------------------
template <int MODE, int RELU>
__global__ __launch_bounds__(256, 2)
void gemm_f16(const uint4* __restrict__ Ah, const uint4* __restrict__ Bh,
              float* __restrict__ C, uint4* __restrict__ FH,
              int Ncols, int K, int nbX,
              size_t sBu4, size_t sCf, int mbPerBatch, size_t sFu4,
              float outScale) {
    extern __shared__ __align__(128) char sm[];
    const int tid = threadIdx.x;
    const int lane = tid & 31;
    const int wid = tid >> 5;
    const int wm = wid >> 2;
    const int wn = wid & 3;
    const int bx = blockIdx.x % nbX;
    const int bz = blockIdx.x / nbX;
    const int by = blockIdx.y;

    Bh += (size_t)bz * sBu4;

    const int nc2 = K >> 5;
    const int nkc = K >> 4;
    const int nnb = Ncols >> 7;
    const uint32_t sbase = smem_u32(sm);

    float acc[4][4][4];
#pragma unroll
    for (int i = 0; i < 4; i++)
#pragma unroll
        for (int j = 0; j < 4; j++)
#pragma unroll
            for (int r = 0; r < 4; r++) acc[i][j][r] = 0.f;

    auto issue = [&](int s, int c) {
        uint32_t sa = sbase + s * 16384 + tid * 16;
        size_t ab = ((size_t)by * nkc + (size_t)(c << 1)) * 256 + tid;
        size_t bb0 = ((size_t)(c << 1) * nnb + bx) * 256 + tid;
        size_t bb1 = bb0 + (size_t)nnb * 256;
        cpa16(sa,         Ah + ab);
        cpa16(sa + 4096,  Ah + ab + 256);
        cpa16(sa + 8192,  Bh + bb0);
        cpa16(sa + 12288, Bh + bb1);
    };

    issue(0, 0); CP_COMMIT();
    issue(1, 1); CP_COMMIT();

    for (int c = 0; c < nc2; ++c) {
        int s = c % 3;
        CP_WAIT1();
        __syncthreads();
        const char* st = sm + s * 16384;
#pragma unroll
        for (int kk = 0; kk < 2; ++kk) {
            const uint4* sAh = (const uint4*)(st + kk * 4096);
            const uint4* sBh = (const uint4*)(st + 8192 + kk * 4096);
            uint4 fAh[4], fBh[2];
#pragma unroll
            for (int i = 0; i < 4; i++)
                fAh[i] = sAh[(wm * 4 + i) * 32 + lane];
#pragma unroll
            for (int q = 0; q < 2; q++)
                fBh[q] = sBh[(wn * 2 + q) * 32 + lane];
#pragma unroll
            for (int i = 0; i < 4; i++) {
#pragma unroll
                for (int j = 0; j < 4; j++) {
                    int q = j >> 1;
                    uint32_t b0 = (j & 1) ? fBh[q].z : fBh[q].x;
                    uint32_t b1 = (j & 1) ? fBh[q].w : fBh[q].y;
                    mma16816(acc[i][j], fAh[i], b0, b1);
                }
            }
        }
        if (c + 2 < nc2) issue((c + 2) % 3, c + 2);
        CP_COMMIT();
    }

    if (RELU) {
#pragma unroll
        for (int i = 0; i < 4; i++)
#pragma unroll
            for (int j = 0; j < 4; j++)
#pragma unroll
                for (int r = 0; r < 4; r++) acc[i][j][r] = fmaxf(acc[i][j][r], 0.f);
    }

    if (MODE == 0) {
        float* Cb = C + (size_t)bz * sCf;
        const int row0 = by * 128 + wm * 64 + (lane >> 2);
        const int colb = bx * 128 + wn * 32 + (lane & 3) * 2;
#pragma unroll
        for (int i = 0; i < 4; i++)
#pragma unroll
            for (int j = 0; j < 4; j++) {
                int r = row0 + i * 16;
                int col = colb + j * 8;
                *reinterpret_cast<float2*>(Cb + (size_t)r * Ncols + col) =
                    make_float2(acc[i][j][0] * outScale, acc[i][j][1] * outScale);
                *reinterpret_cast<float2*>(Cb + (size_t)(r + 8) * Ncols + col) =
                    make_float2(acc[i][j][2] * outScale, acc[i][j][3] * outScale);
            }
    } else if (MODE == 1) {
        // emit A-frags (hi) for next GEMM (C-frag layout == A-frag layout)
        const int nkNext = Ncols >> 4;
        const size_t mb = (size_t)bz * mbPerBatch + by;
#pragma unroll
        for (int i = 0; i < 4; i++)
#pragma unroll
            for (int jp = 0; jp < 2; jp++) {
                float* a0 = acc[i][2 * jp];
                float* a1 = acc[i][2 * jp + 1];
                int kcg = bx * 8 + wn * 2 + jp;
                size_t di = (mb * nkNext + kcg) * 256 + (wm * 4 + i) * 32 + lane;
                FH[di] = make_uint4(pk(a0[0], a0[1]), pk(a0[2], a0[3]),
                                    pk(a1[0], a1[1]), pk(a1[2], a1[3]));
            }
    } else {
        // MODE 2: emit B-frags (hi) for next GEMM via smem transpose.
        CP_WAIT0();
        __syncthreads();
        float* sf = (float*)sm;  // 128 x 132 fp32
        const int r0 = wm * 64 + (lane >> 2);
        const int c0 = wn * 32 + (lane & 3) * 2;
#pragma unroll
        for (int i = 0; i < 4; i++)
#pragma unroll
            for (int j = 0; j < 4; j++) {
                int rr = r0 + i * 16, cc = c0 + j * 8;
                sf[rr * 132 + cc] = acc[i][j][0];
                sf[rr * 132 + cc + 1] = acc[i][j][1];
                sf[(rr + 8) * 132 + cc] = acc[i][j][2];
                sf[(rr + 8) * 132 + cc + 1] = acc[i][j][3];
            }
        __syncthreads();
        const int batchO = by >> 5;
        const int mbLoc = by & 31;
        const int jj = tid >> 5;
        const int ln = tid & 31;
        const int n0 = 16 * jj + (ln >> 2);
        const int k0b = (ln & 3) * 2;
#pragma unroll
        for (int kb = 0; kb < 8; kb++) {
            int k0 = kb * 16 + k0b;
            float e[8];
            e[0] = sf[k0 * 132 + n0];
            e[1] = sf[(k0 + 1) * 132 + n0];
            e[2] = sf[(k0 + 8) * 132 + n0];
            e[3] = sf[(k0 + 9) * 132 + n0];
            e[4] = sf[k0 * 132 + n0 + 8];
            e[5] = sf[(k0 + 1) * 132 + n0 + 8];
            e[6] = sf[(k0 + 8) * 132 + n0 + 8];
            e[7] = sf[(k0 + 9) * 132 + n0 + 8];
            int kc = mbLoc * 8 + kb;
            size_t di = (size_t)batchO * sFu4 + ((size_t)kc * nbX + bx) * 256 + tid;
            FH[di] = make_uint4(pk(e[0], e[1]), pk(e[2], e[3]),
                                pk(e[4], e[5]), pk(e[6], e[7]));
        }
    }
}

// ---------------------------------------------------------------------------
template <int MODE, int RELU>
static void launch_gemm(int M, int Ncols, int K,
                        const uint4* Ah, const uint4* Bh,
                        float* C, uint4* FH,
                        int batch, size_t sBu4, size_t sCf,
                        int mbPerBatch, size_t sFu4, float outScale) {
    int nbX = Ncols / 128;
    dim3 g(nbX * batch, M / 128);
    // MODE2 epilogue reuses smem as 128x132 fp32 = 67584 B; others need 48KB.
    int smem = (MODE == 2) ? 69632 : 49152;
    cudaFuncSetAttribute(gemm_f16<MODE, RELU>,
                         cudaFuncAttributeMaxDynamicSharedMemorySize, smem);
    gemm_f16<MODE, RELU><<<g, 256, smem>>>(
        Ah, Bh, C, FH, Ncols, K, nbX, sBu4, sCf, mbPerBatch, sFu4, outScale);
}

extern "C" void kernel_launch(void* const* d_in, const int* in_sizes, int n_in,
                              void* d_out, int out_size) {
    const float* x   = (const float*)d_in[0];  // [B, N, 256]
    const float* adj = (const float*)d_in[1];
    const float* S   = (const float*)d_in[2];
    const float* W1  = (const float*)d_in[3];  // [256, 512]
    const float* W2  = (const float*)d_in[4];  // [512, 1024]
    const float* W3  = (const float*)d_in[5];  // [1024, 256]
    float* out = (float*)d_out;                // [B, N, 256]

    uint4 *AwH, *FaH, *FbH, *WH;
    cudaGetSymbolAddress((void**)&AwH, g_AwH);
    cudaGetSymbolAddress((void**)&FaH, g_FaH);
    cudaGetSymbolAddress((void**)&FbH, g_FbH);
    cudaGetSymbolAddress((void**)&WH, g_WH);

    const size_t sX  = (size_t)NN * 256 / 8;   // per-batch u4 strides
    const size_t sH1 = (size_t)NN * 512 / 8;
    const size_t sS3 = (size_t)NN * 256 / 8;

    // One-time preps (all hi-only)
    prep_A_tile<<<dim3(NN / 64, NN / 128), 256>>>(adj, S, AwH, NN, NN);
    prep_B_tile<<<dim3(2, NN / 32, BB), 256>>>(x, FbH, NN, 256,
                                               (size_t)NN * 256, sX, XSCALE);
    prep_B_tile<<<dim3(4, 8, 1), 256>>>(W1, WH, 256, 512, 0, 0, 1.0f);
    prep_B_tile<<<dim3(8, 16, 1), 256>>>(W2, WH + 16384, 512, 1024, 0, 0, 1.0f);
    prep_B_tile<<<dim3(2, 32, 1), 256>>>(W3, WH + 81920, 1024, 256, 0, 0, 1.0f);

    // G1: t1 = Aw @ x -> A-frags (Fa).
    launch_gemm<1, 0>(NN, 256, NN, AwH, FbH, nullptr, FaH,
                      BB, sX, 0, NN / 128, 0, 1.0f);
    // G2: h1 = relu(t1 @ W1) -> B-frags (Fb).
    launch_gemm<2, 1>(BB * NN, 512, 256, FaH, WH, nullptr, FbH,
                      1, 0, 0, 0, sH1, 1.0f);
    // G3: t2 = Aw @ h1 -> A-frags (Fa).
    launch_gemm<1, 0>(NN, 512, NN, AwH, FbH, nullptr, FaH,
                      BB, sH1, 0, NN / 128, 0, 1.0f);
    // G4: h2 = relu(t2 @ W2) -> A-frags (Fb).
    launch_gemm<1, 1>(BB * NN, 1024, 512, FaH, WH + 16384, nullptr, FbH,
                      1, 0, 0, 0, 0, 1.0f);
    // G5: s3 = h2 @ W3 -> B-frags (Fa).
    launch_gemm<2, 0>(BB * NN, 256, 1024, FbH, WH + 81920, nullptr, FaH,
                      1, 0, 0, 0, sS3, 1.0f);
    // G6: out = 64 * (Aw @ s3) -> fp32.
    launch_gemm<0, 0>(NN, 256, NN, AwH, FaH, out, nullptr,
                      BB, sS3, (size_t)NN * 256, 0, 0, OSCALE);
}

// round 13
// speedup vs baseline: 1.4275x; 1.0403x over previous
#include <cuda_runtime.h>
#include <cuda_fp16.h>
#include <cstdint>

// GCN — reassociated 3-layer GCN, fp16 hi-only mma.sync, globally scaled.
// x' = x/64; out *= 64 (relu positively homogeneous).
// G1: t1=Aw@x   G2: h1=relu(t1@W1)   G3: t2=Aw@h1
// G4: h2=relu(t2@W2)   G5: s3=h2@W3   G6: out=64*Aw@s3
// All 1-product fp16-hi; fp32 accum. 4-stage cp.async pipeline, early issue.

#define NN 4096
#define BB 4
#define XSCALE (1.0f / 64.0f)
#define OSCALE 64.0f

// Fragment-tiled storage: A blocks 128m x 16k = 256 uint4 (block = mb*nkc+kc),
// B blocks 16k x 128n = 256 uint4 (block = kc*nnb+nb).
__device__ uint4 g_AwH[(size_t)NN * NN / 8];
__device__ uint4 g_FaH[(size_t)BB * NN * 1024 / 8];  // ping
__device__ uint4 g_FbH[(size_t)BB * NN * 1024 / 8];  // pong
__device__ uint4 g_WH[114688];  // W1@0, W2@16384, W3@81920

// ---------------------------------------------------------------------------
__device__ __forceinline__ uint32_t smem_u32(const void* p) {
    uint32_t a;
    asm("{ .reg .u64 t; cvta.to.shared.u64 t, %1; cvt.u32.u64 %0, t; }"
        : "=r"(a) : "l"(p));
    return a;
}
__device__ __forceinline__ uint32_t pk(float a, float b) {
    __half2 t = __floats2half2_rn(a, b);
    return *reinterpret_cast<uint32_t*>(&t);
}
__device__ __forceinline__ void cpa16(uint32_t saddr, const void* gaddr) {
    asm volatile("cp.async.cg.shared.global [%0], [%1], 16;"
                 :: "r"(saddr), "l"(gaddr));
}
#define CP_COMMIT() asm volatile("cp.async.commit_group;" ::: "memory")
#define CP_WAIT2()  asm volatile("cp.async.wait_group 2;" ::: "memory")
#define CP_WAIT0()  asm volatile("cp.async.wait_group 0;" ::: "memory")

__device__ __forceinline__ void mma16816(float* c, const uint4& a,
                                         uint32_t b0, uint32_t b1) {
    asm volatile(
        "mma.sync.aligned.m16n8k16.row.col.f32.f16.f16.f32 "
        "{%0,%1,%2,%3},{%4,%5,%6,%7},{%8,%9},{%0,%1,%2,%3};"
        : "+f"(c[0]), "+f"(c[1]), "+f"(c[2]), "+f"(c[3])
        : "r"(a.x), "r"(a.y), "r"(a.z), "r"(a.w), "r"(b0), "r"(b1));
}

// ---------------------------------------------------------------------------
// prep_A_tile: Aw = adj .* S -> A-frag hi only. Coalesced 128x64 tile stage.
// grid: (K/64, M/128), 256 threads.
// ---------------------------------------------------------------------------
__global__ __launch_bounds__(256)
void prep_A_tile(const float* __restrict__ src, const float* __restrict__ mul,
                 uint4* __restrict__ dhi, int M, int K) {
    __shared__ float smt[128][68];
    const int tid = threadIdx.x;
    const int kcb = blockIdx.x;
    const size_t mb = blockIdx.y;
    const int colBase = kcb * 64;
    const size_t rowBase = mb * 128;

    const int c4 = tid & 15;
    const int r0 = tid >> 4;
#pragma unroll
    for (int i = 0; i < 8; i++) {
        int r = r0 + i * 16;
        const float4 v = ((const float4*)(src + (rowBase + r) * K + colBase))[c4];
        const float4 s = ((const float4*)(mul + (rowBase + r) * K + colBase))[c4];
        float4 o = make_float4(v.x * s.x, v.y * s.y, v.z * s.z, v.w * s.w);
        *(float4*)&smt[r][c4 * 4] = o;
    }
    __syncthreads();

    const int lane = tid & 31;
    const int mt = tid >> 5;
    const int rr = mt * 16 + (lane >> 2);
    const int cb = (lane & 3) * 2;
    const int nkc = K >> 4;
#pragma unroll
    for (int kb = 0; kb < 4; kb++) {
        int c0 = kb * 16 + cb;
        uint4 H = make_uint4(
            pk(smt[rr][c0],     smt[rr][c0 + 1]),
            pk(smt[rr + 8][c0], smt[rr + 8][c0 + 1]),
            pk(smt[rr][c0 + 8], smt[rr][c0 + 9]),
            pk(smt[rr + 8][c0 + 8], smt[rr + 8][c0 + 9]));
        dhi[(mb * nkc + (size_t)(kcb * 4 + kb)) * 256 + tid] = H;
    }
}

// ---------------------------------------------------------------------------
// B-prep tile body: one 32x128 tile of src [K,Ncols] * scale -> B-frag hi.
// ---------------------------------------------------------------------------
__device__ __forceinline__ void prep_B_body(const float* __restrict__ src,
                                            uint4* __restrict__ dhi,
                                            int Ncols, int nb, int kcb,
                                            float scale) {
    __shared__ float smt[32][132];
    const int tid = threadIdx.x;
    const int c4 = tid & 31;
    const int r0 = tid >> 5;
#pragma unroll
    for (int i = 0; i < 4; i++) {
        int r = r0 + i * 8;
        float4 v = ((const float4*)(src + (size_t)(kcb * 32 + r) * Ncols +
                                    nb * 128))[c4];
        v.x *= scale; v.y *= scale; v.z *= scale; v.w *= scale;
        *(float4*)&smt[r][c4 * 4] = v;
    }
    __syncthreads();

    const int lane = tid & 31;
    const int j = tid >> 5;
    const int n0 = j * 16 + (lane >> 2);
    const int k0b = (lane & 3) * 2;
    const int nnb = Ncols >> 7;
#pragma unroll
    for (int kk = 0; kk < 2; kk++) {
        int k0 = kk * 16 + k0b;
        float e[8];
        e[0] = smt[k0][n0];     e[1] = smt[k0 + 1][n0];
        e[2] = smt[k0 + 8][n0]; e[3] = smt[k0 + 9][n0];
        e[4] = smt[k0][n0 + 8];     e[5] = smt[k0 + 1][n0 + 8];
        e[6] = smt[k0 + 8][n0 + 8]; e[7] = smt[k0 + 9][n0 + 8];
        size_t blk = (size_t)(kcb * 2 + kk) * nnb + nb;
        dhi[blk * 256 + tid] = make_uint4(pk(e[0], e[1]), pk(e[2], e[3]),
                                          pk(e[4], e[5]), pk(e[6], e[7]));
    }
}

// ---------------------------------------------------------------------------
// Merged B-prep: one launch handles x (scaled), W1, W2, W3.
// Block ranges (hardcoded shapes):
//   [0,1024):    x  [4096,256]  batch 4 (256 blocks each: nb=2, kcb=128)
//   [1024,1056): W1 [256,512]   (nb=4, kcb=8)
//   [1056,1184): W2 [512,1024]  (nb=8, kcb=16)
//   [1184,1248): W3 [1024,256]  (nb=2, kcb=32)
// ---------------------------------------------------------------------------
__global__ __launch_bounds__(256)
void prep_B_all(const float* __restrict__ x, const float* __restrict__ W1,
                const float* __restrict__ W2, const float* __restrict__ W3,
                uint4* __restrict__ FbH, uint4* __restrict__ WH) {
    const int bid = blockIdx.x;
    if (bid < 1024) {
        int bz = bid >> 8;
        int r = bid & 255;
        prep_B_body(x + (size_t)bz * NN * 256,
                    FbH + (size_t)bz * (NN * 256 / 8),
                    256, r & 1, r >> 1, XSCALE);
    } else if (bid < 1056) {
        int r = bid - 1024;
        prep_B_body(W1, WH, 512, r & 3, r >> 2, 1.0f);
    } else if (bid < 1184) {
        int r = bid - 1056;
        prep_B_body(W2, WH + 16384, 1024, r & 7, r >> 3, 1.0f);
    } else {
        int r = bid - 1184;
        prep_B_body(W3, WH + 81920, 256, r & 1, r >> 1, 1.0f);
    }
}

// ---------------------------------------------------------------------------
// GEMM: BM=128, BN=128, BK=32, 4-stage cp.async (16KB/stage), 8 warps (2x4),
// warp tile 64x32, 1 product (A-hi x B-hi). Early issue after sync.
// MODE 0: fp32 store (scaled).  MODE 1: emit A-frags (hi).
// MODE 2: emit B-frags (hi, smem transpose).  RELU before emission.
// grid: x = nbX*batch (bx = x%nbX, bz = x/nbX), y = M/128.
// ---------------------------------------------------------------------------
template <int MODE, int RELU>
__global__ __launch_bounds__(256, 2)
void gemm_f16(const uint4* __restrict__ Ah, const uint4* __restrict__ Bh,
              float* __restrict__ C, uint4* __restrict__ FH,
              int Ncols, int K, int nbX,
              size_t sBu4, size_t sCf, int mbPerBatch, size_t sFu4,
              float outScale) {
    extern __shared__ __align__(128) char sm[];
    const int tid = threadIdx.x;
    const int lane = tid & 31;
    const int wid = tid >> 5;
    const int wm = wid >> 2;
    const int wn = wid & 3;
    const int bx = blockIdx.x % nbX;
    const int bz = blockIdx.x / nbX;
    const int by = blockIdx.y;

    Bh += (size_t)bz * sBu4;

    const int nc2 = K >> 5;
    const int nkc = K >> 4;
    const int nnb = Ncols >> 7;
    const uint32_t sbase = smem_u32(sm);

    float acc[4][4][4];
#pragma unroll
    for (int i = 0; i < 4; i++)
#pragma unroll
        for (int j = 0; j < 4; j++)
#pragma unroll
            for (int r = 0; r < 4; r++) acc[i][j][r] = 0.f;

    auto issue = [&](int s, int c) {
        uint32_t sa = sbase + s * 16384 + tid * 16;
        size_t ab = ((size_t)by * nkc + (size_t)(c << 1)) * 256 + tid;
        size_t bb0 = ((size_t)(c << 1) * nnb + bx) * 256 + tid;
        size_t bb1 = bb0 + (size_t)nnb * 256;
        cpa16(sa,         Ah + ab);
        cpa16(sa + 4096,  Ah + ab + 256);
        cpa16(sa + 8192,  Bh + bb0);
        cpa16(sa + 12288, Bh + bb1);
    };

    issue(0, 0); CP_COMMIT();
    issue(1, 1); CP_COMMIT();
    issue(2, 2); CP_COMMIT();

    for (int c = 0; c < nc2; ++c) {
        int s = c & 3;
        CP_WAIT2();
        __syncthreads();
        // Early issue: stage (c+3)&3 == (c-1)&3 was fully consumed last chunk.
        if (c + 3 < nc2) issue((c + 3) & 3, c + 3);
        CP_COMMIT();

        const char* st = sm + s * 16384;
#pragma unroll
        for (int kk = 0; kk < 2; ++kk) {
            const uint4* sAh = (const uint4*)(st + kk * 4096);
            const uint4* sBh = (const uint4*)(st + 8192 + kk * 4096);
            uint4 fAh[4], fBh[2];
#pragma unroll
            for (int i = 0; i < 4; i++)
                fAh[i] = sAh[(wm * 4 + i) * 32 + lane];
#pragma unroll
            for (int q = 0; q < 2; q++)
                fBh[q] = sBh[(wn * 2 + q) * 32 + lane];
#pragma unroll
            for (int i = 0; i < 4; i++) {
#pragma unroll
                for (int j = 0; j < 4; j++) {
                    int q = j >> 1;
                    uint32_t b0 = (j & 1) ? fBh[q].z : fBh[q].x;
                    uint32_t b1 = (j & 1) ? fBh[q].w : fBh[q].y;
                    mma16816(acc[i][j], fAh[i], b0, b1);
                }
            }
        }
    }

    if (RELU) {
#pragma unroll
        for (int i = 0; i < 4; i++)
#pragma unroll
            for (int j = 0; j < 4; j++)
#pragma unroll
                for (int r = 0; r < 4; r++) acc[i][j][r] = fmaxf(acc[i][j][r], 0.f);
    }

    if (MODE == 0) {
        float* Cb = C + (size_t)bz * sCf;
        const int row0 = by * 128 + wm * 64 + (lane >> 2);
        const int colb = bx * 128 + wn * 32 + (lane & 3) * 2;
#pragma unroll
        for (int i = 0; i < 4; i++)
#pragma unroll
            for (int j = 0; j < 4; j++) {
                int r = row0 + i * 16;
                int col = colb + j * 8;
                *reinterpret_cast<float2*>(Cb + (size_t)r * Ncols + col) =
                    make_float2(acc[i][j][0] * outScale, acc[i][j][1] * outScale);
                *reinterpret_cast<float2*>(Cb + (size_t)(r + 8) * Ncols + col) =
                    make_float2(acc[i][j][2] * outScale, acc[i][j][3] * outScale);
            }
    } else if (MODE == 1) {
        // emit A-frags (hi) for next GEMM (C-frag layout == A-frag layout)
        const int nkNext = Ncols >> 4;
        const size_t mb = (size_t)bz * mbPerBatch + by;
#pragma unroll
        for (int i = 0; i < 4; i++)
#pragma unroll
            for (int jp = 0; jp < 2; jp++) {
                float* a0 = acc[i][2 * jp];
                float* a1 = acc[i][2 * jp + 1];
                int kcg = bx * 8 + wn * 2 + jp;
                size_t di = (mb * nkNext + kcg) * 256 + (wm * 4 + i) * 32 + lane;
                FH[di] = make_uint4(pk(a0[0], a0[1]), pk(a0[2], a0[3]),
                                    pk(a1[0], a1[1]), pk(a1[2], a1[3]));
            }
    } else {
        // MODE 2: emit B-frags (hi) for next GEMM via smem transpose.
        CP_WAIT0();
        __syncthreads();
        float* sf = (float*)sm;  // 128 x 132 fp32
        const int r0 = wm * 64 + (lane >> 2);
        const int c0 = wn * 32 + (lane & 3) * 2;
#pragma unroll
        for (int i = 0; i < 4; i++)
#pragma unroll
            for (int j = 0; j < 4; j++) {
                int rr = r0 + i * 16, cc = c0 + j * 8;
                sf[rr * 132 + cc] = acc[i][j][0];
                sf[rr * 132 + cc + 1] = acc[i][j][1];
                sf[(rr + 8) * 132 + cc] = acc[i][j][2];
                sf[(rr + 8) * 132 + cc + 1] = acc[i][j][3];
            }
        __syncthreads();
        const int batchO = by >> 5;
        const int mbLoc = by & 31;
        const int jj = tid >> 5;
        const int ln = tid & 31;
        const int n0 = 16 * jj + (ln >> 2);
        const int k0b = (ln & 3) * 2;
#pragma unroll
        for (int kb = 0; kb < 8; kb++) {
            int k0 = kb * 16 + k0b;
            float e[8];
            e[0] = sf[k0 * 132 + n0];
            e[1] = sf[(k0 + 1) * 132 + n0];
            e[2] = sf[(k0 + 8) * 132 + n0];
            e[3] = sf[(k0 + 9) * 132 + n0];
            e[4] = sf[k0 * 132 + n0 + 8];
            e[5] = sf[(k0 + 1) * 132 + n0 + 8];
            e[6] = sf[(k0 + 8) * 132 + n0 + 8];
            e[7] = sf[(k0 + 9) * 132 + n0 + 8];
            int kc = mbLoc * 8 + kb;
            size_t di = (size_t)batchO * sFu4 + ((size_t)kc * nbX + bx) * 256 + tid;
            FH[di] = make_uint4(pk(e[0], e[1]), pk(e[2], e[3]),
                                pk(e[4], e[5]), pk(e[6], e[7]));
        }
    }
}

// ---------------------------------------------------------------------------
template <int MODE, int RELU>
static void launch_gemm(int M, int Ncols, int K,
                        const uint4* Ah, const uint4* Bh,
                        float* C, uint4* FH,
                        int batch, size_t sBu4, size_t sCf,
                        int mbPerBatch, size_t sFu4, float outScale) {
    int nbX = Ncols / 128;
    dim3 g(nbX * batch, M / 128);
    // 4 stages x 16KB = 64KB; MODE2 transpose needs 128x132 fp32 = 67584.
    int smem = (MODE == 2) ? 69632 : 65536;
    cudaFuncSetAttribute(gemm_f16<MODE, RELU>,
                         cudaFuncAttributeMaxDynamicSharedMemorySize, smem);
    gemm_f16<MODE, RELU><<<g, 256, smem>>>(
        Ah, Bh, C, FH, Ncols, K, nbX, sBu4, sCf, mbPerBatch, sFu4, outScale);
}

extern "C" void kernel_launch(void* const* d_in, const int* in_sizes, int n_in,
                              void* d_out, int out_size) {
    const float* x   = (const float*)d_in[0];  // [B, N, 256]
    const float* adj = (const float*)d_in[1];
    const float* S   = (const float*)d_in[2];
    const float* W1  = (const float*)d_in[3];  // [256, 512]
    const float* W2  = (const float*)d_in[4];  // [512, 1024]
    const float* W3  = (const float*)d_in[5];  // [1024, 256]
    float* out = (float*)d_out;                // [B, N, 256]

    uint4 *AwH, *FaH, *FbH, *WH;
    cudaGetSymbolAddress((void**)&AwH, g_AwH);
    cudaGetSymbolAddress((void**)&FaH, g_FaH);
    cudaGetSymbolAddress((void**)&FbH, g_FbH);
    cudaGetSymbolAddress((void**)&WH, g_WH);

    const size_t sX  = (size_t)NN * 256 / 8;   // per-batch u4 strides
    const size_t sH1 = (size_t)NN * 512 / 8;
    const size_t sS3 = (size_t)NN * 256 / 8;

    // One-time preps
    prep_A_tile<<<dim3(NN / 64, NN / 128), 256>>>(adj, S, AwH, NN, NN);
    prep_B_all<<<1248, 256>>>(x, W1, W2, W3, FbH, WH);

    // G1: t1 = Aw @ x -> A-frags (Fa).
    launch_gemm<1, 0>(NN, 256, NN, AwH, FbH, nullptr, FaH,
                      BB, sX, 0, NN / 128, 0, 1.0f);
    // G2: h1 = relu(t1 @ W1) -> B-frags (Fb).
    launch_gemm<2, 1>(BB * NN, 512, 256, FaH, WH, nullptr, FbH,
                      1, 0, 0, 0, sH1, 1.0f);
    // G3: t2 = Aw @ h1 -> A-frags (Fa).
    launch_gemm<1, 0>(NN, 512, NN, AwH, FbH, nullptr, FaH,
                      BB, sH1, 0, NN / 128, 0, 1.0f);
    // G4: h2 = relu(t2 @ W2) -> A-frags (Fb).
    launch_gemm<1, 1>(BB * NN, 1024, 512, FaH, WH + 16384, nullptr, FbH,
                      1, 0, 0, 0, 0, 1.0f);
    // G5: s3 = h2 @ W3 -> B-frags (Fa).
    launch_gemm<2, 0>(BB * NN, 256, 1024, FbH, WH + 81920, nullptr, FaH,
                      1, 0, 0, 0, sS3, 1.0f);
    // G6: out = 64 * (Aw @ s3) -> fp32.
    launch_gemm<0, 0>(NN, 256, NN, AwH, FaH, out, nullptr,
                      BB, sS3, (size_t)NN * 256, 0, 0, OSCALE);
}

// round 14
// speedup vs baseline: 1.4684x; 1.0287x over previous
#include <cuda_runtime.h>
#include <cuda_fp16.h>
#include <cstdint>

// GCN — reassociated 3-layer GCN, fp16 hi-only mma.sync, globally scaled.
// x' = x/64; out *= 64 (relu positively homogeneous).
// G1: t1=Aw@x   G2: h1=relu(t1@W1)   G3: t2=Aw@h1
// G4: h2=relu(t2@W2)   G5: s3=h2@W3   G6: out=64*Aw@s3
// All 1-product fp16-hi; fp32 accum. 5-stage cp.async, pointer-stride issue.

#define NN 4096
#define BB 4
#define XSCALE (1.0f / 64.0f)
#define OSCALE 64.0f

// Fragment-tiled storage: A blocks 128m x 16k = 256 uint4 (block = mb*nkc+kc),
// B blocks 16k x 128n = 256 uint4 (block = kc*nnb+nb).
__device__ uint4 g_AwH[(size_t)NN * NN / 8];
__device__ uint4 g_FaH[(size_t)BB * NN * 1024 / 8];  // ping
__device__ uint4 g_FbH[(size_t)BB * NN * 1024 / 8];  // pong
__device__ uint4 g_WH[114688];  // W1@0, W2@16384, W3@81920

// ---------------------------------------------------------------------------
__device__ __forceinline__ uint32_t smem_u32(const void* p) {
    uint32_t a;
    asm("{ .reg .u64 t; cvta.to.shared.u64 t, %1; cvt.u32.u64 %0, t; }"
        : "=r"(a) : "l"(p));
    return a;
}
__device__ __forceinline__ uint32_t pk(float a, float b) {
    __half2 t = __floats2half2_rn(a, b);
    return *reinterpret_cast<uint32_t*>(&t);
}
__device__ __forceinline__ void cpa16(uint32_t saddr, const void* gaddr) {
    asm volatile("cp.async.cg.shared.global [%0], [%1], 16;"
                 :: "r"(saddr), "l"(gaddr));
}
#define CP_COMMIT() asm volatile("cp.async.commit_group;" ::: "memory")
#define CP_WAIT3()  asm volatile("cp.async.wait_group 3;" ::: "memory")
#define CP_WAIT0()  asm volatile("cp.async.wait_group 0;" ::: "memory")

__device__ __forceinline__ void mma16816(float* c, const uint4& a,
                                         uint32_t b0, uint32_t b1) {
    asm volatile(
        "mma.sync.aligned.m16n8k16.row.col.f32.f16.f16.f32 "
        "{%0,%1,%2,%3},{%4,%5,%6,%7},{%8,%9},{%0,%1,%2,%3};"
        : "+f"(c[0]), "+f"(c[1]), "+f"(c[2]), "+f"(c[3])
        : "r"(a.x), "r"(a.y), "r"(a.z), "r"(a.w), "r"(b0), "r"(b1));
}

// ---------------------------------------------------------------------------
// Prep bodies (shared-memory staged, coalesced float4 reads).
// ---------------------------------------------------------------------------
__device__ __forceinline__ void prep_A_body(const float* __restrict__ src,
                                            const float* __restrict__ mul,
                                            uint4* __restrict__ dhi,
                                            int K, int kcb, int mb,
                                            float* smraw) {
    float (*smt)[68] = (float (*)[68])smraw;
    const int tid = threadIdx.x;
    const int colBase = kcb * 64;
    const size_t rowBase = (size_t)mb * 128;

    const int c4 = tid & 15;
    const int r0 = tid >> 4;
#pragma unroll
    for (int i = 0; i < 8; i++) {
        int r = r0 + i * 16;
        const float4 v = ((const float4*)(src + (rowBase + r) * K + colBase))[c4];
        const float4 s = ((const float4*)(mul + (rowBase + r) * K + colBase))[c4];
        *(float4*)&smt[r][c4 * 4] =
            make_float4(v.x * s.x, v.y * s.y, v.z * s.z, v.w * s.w);
    }
    __syncthreads();

    const int lane = tid & 31;
    const int mt = tid >> 5;
    const int rr = mt * 16 + (lane >> 2);
    const int cb = (lane & 3) * 2;
    const int nkc = K >> 4;
#pragma unroll
    for (int kb = 0; kb < 4; kb++) {
        int c0 = kb * 16 + cb;
        uint4 H = make_uint4(
            pk(smt[rr][c0],     smt[rr][c0 + 1]),
            pk(smt[rr + 8][c0], smt[rr + 8][c0 + 1]),
            pk(smt[rr][c0 + 8], smt[rr][c0 + 9]),
            pk(smt[rr + 8][c0 + 8], smt[rr + 8][c0 + 9]));
        dhi[((size_t)mb * nkc + (size_t)(kcb * 4 + kb)) * 256 + tid] = H;
    }
}

__device__ __forceinline__ void prep_B_body(const float* __restrict__ src,
                                            uint4* __restrict__ dhi,
                                            int Ncols, int nb, int kcb,
                                            float scale, float* smraw) {
    float (*smt)[132] = (float (*)[132])smraw;
    const int tid = threadIdx.x;
    const int c4 = tid & 31;
    const int r0 = tid >> 5;
#pragma unroll
    for (int i = 0; i < 4; i++) {
        int r = r0 + i * 8;
        float4 v = ((const float4*)(src + (size_t)(kcb * 32 + r) * Ncols +
                                    nb * 128))[c4];
        v.x *= scale; v.y *= scale; v.z *= scale; v.w *= scale;
        *(float4*)&smt[r][c4 * 4] = v;
    }
    __syncthreads();

    const int lane = tid & 31;
    const int j = tid >> 5;
    const int n0 = j * 16 + (lane >> 2);
    const int k0b = (lane & 3) * 2;
    const int nnb = Ncols >> 7;
#pragma unroll
    for (int kk = 0; kk < 2; kk++) {
        int k0 = kk * 16 + k0b;
        float e[8];
        e[0] = smt[k0][n0];     e[1] = smt[k0 + 1][n0];
        e[2] = smt[k0 + 8][n0]; e[3] = smt[k0 + 9][n0];
        e[4] = smt[k0][n0 + 8];     e[5] = smt[k0 + 1][n0 + 8];
        e[6] = smt[k0 + 8][n0 + 8]; e[7] = smt[k0 + 9][n0 + 8];
        size_t blk = (size_t)(kcb * 2 + kk) * nnb + nb;
        dhi[blk * 256 + tid] = make_uint4(pk(e[0], e[1]), pk(e[2], e[3]),
                                          pk(e[4], e[5]), pk(e[6], e[7]));
    }
}

// ---------------------------------------------------------------------------
// Fused prep: ONE launch does Aw, x, W1, W2, W3.
//   [0,2048):    Aw [4096,4096] .* S   (kcb = r&63, mb = r>>6)
//   [2048,3072): x  [4096,256] x4 batch (per batch 256: nb=r&1, kcb=r>>1)
//   [3072,3104): W1 [256,512]   (nb=r&3, kcb=r>>2)
//   [3104,3232): W2 [512,1024]  (nb=r&7, kcb=r>>3)
//   [3232,3296): W3 [1024,256]  (nb=r&1, kcb=r>>1)
// ---------------------------------------------------------------------------
__global__ __launch_bounds__(256)
void prep_all(const float* __restrict__ adj, const float* __restrict__ S,
              const float* __restrict__ x, const float* __restrict__ W1,
              const float* __restrict__ W2, const float* __restrict__ W3,
              uint4* __restrict__ AwH, uint4* __restrict__ FbH,
              uint4* __restrict__ WH) {
    __shared__ float smraw[128 * 68];
    const int bid = blockIdx.x;
    if (bid < 2048) {
        prep_A_body(adj, S, AwH, NN, bid & 63, bid >> 6, smraw);
    } else if (bid < 3072) {
        int r = bid - 2048;
        int bz = r >> 8;
        r &= 255;
        prep_B_body(x + (size_t)bz * NN * 256,
                    FbH + (size_t)bz * (NN * 256 / 8),
                    256, r & 1, r >> 1, XSCALE, smraw);
    } else if (bid < 3104) {
        int r = bid - 3072;
        prep_B_body(W1, WH, 512, r & 3, r >> 2, 1.0f, smraw);
    } else if (bid < 3232) {
        int r = bid - 3104;
        prep_B_body(W2, WH + 16384, 1024, r & 7, r >> 3, 1.0f, smraw);
    } else {
        int r = bid - 3232;
        prep_B_body(W3, WH + 81920, 256, r & 1, r >> 1, 1.0f, smraw);
    }
}

// ---------------------------------------------------------------------------
// GEMM: BM=128, BN=128, BK=32, 5-stage cp.async (16KB/stage), 8 warps (2x4),
// warp tile 64x32, 1 product (A-hi x B-hi). Pointer-stride issue.
// MODE 0: fp32 store (scaled).  MODE 1: emit A-frags (hi).
// MODE 2: emit B-frags (hi, smem transpose).  RELU before emission.
// grid: x = nbX*batch (bx = x%nbX, bz = x/nbX), y = M/128.
// ---------------------------------------------------------------------------
template <int MODE, int RELU>
__global__ __launch_bounds__(256, 2)
void gemm_f16(const uint4* __restrict__ Ah, const uint4* __restrict__ Bh,
              float* __restrict__ C, uint4* __restrict__ FH,
              int Ncols, int K, int nbX,
              size_t sBu4, size_t sCf, int mbPerBatch, size_t sFu4,
              float outScale) {
    extern __shared__ __align__(128) char sm[];
    const int tid = threadIdx.x;
    const int lane = tid & 31;
    const int wid = tid >> 5;
    const int wm = wid >> 2;
    const int wn = wid & 3;
    const int bx = blockIdx.x % nbX;
    const int bz = blockIdx.x / nbX;
    const int by = blockIdx.y;

    const int nc2 = K >> 5;
    const int nkc = K >> 4;
    const int nnb = Ncols >> 7;

    // Pointer-stride issue state
    const uint32_t saBase = smem_u32(sm) + tid * 16;
    const uint4* Ap = Ah + (size_t)by * nkc * 256 + tid;
    const uint4* Bp = Bh + (size_t)bz * sBu4 + (size_t)bx * 256 + tid;
    const size_t bHalf = (size_t)nnb * 256;   // one 16-k block row of B
    const size_t bStep = bHalf * 2;           // per 32-k chunk

    float acc[4][4][4];
#pragma unroll
    for (int i = 0; i < 4; i++)
#pragma unroll
        for (int j = 0; j < 4; j++)
#pragma unroll
            for (int r = 0; r < 4; r++) acc[i][j][r] = 0.f;

    auto issue = [&](int s) {
        uint32_t sa = saBase + s * 16384;
        cpa16(sa,         Ap);
        cpa16(sa + 4096,  Ap + 256);
        cpa16(sa + 8192,  Bp);
        cpa16(sa + 12288, Bp + bHalf);
        Ap += 512;
        Bp += bStep;
        CP_COMMIT();
    };

    issue(0); issue(1); issue(2); issue(3);

    int sload = 4;   // next stage slot to fill (wraps mod 5)
    int scomp = 0;   // stage being computed
    for (int c = 0; c < nc2; ++c) {
        CP_WAIT3();
        __syncthreads();
        if (c + 4 < nc2) {
            issue(sload);
            if (++sload == 5) sload = 0;
        }

        const char* st = sm + scomp * 16384;
        if (++scomp == 5) scomp = 0;
#pragma unroll
        for (int kk = 0; kk < 2; ++kk) {
            const uint4* sAh = (const uint4*)(st + kk * 4096);
            const uint4* sBh = (const uint4*)(st + 8192 + kk * 4096);
            uint4 fAh[4], fBh[2];
#pragma unroll
            for (int i = 0; i < 4; i++)
                fAh[i] = sAh[(wm * 4 + i) * 32 + lane];
#pragma unroll
            for (int q = 0; q < 2; q++)
                fBh[q] = sBh[(wn * 2 + q) * 32 + lane];
#pragma unroll
            for (int i = 0; i < 4; i++) {
#pragma unroll
                for (int j = 0; j < 4; j++) {
                    int q = j >> 1;
                    uint32_t b0 = (j & 1) ? fBh[q].z : fBh[q].x;
                    uint32_t b1 = (j & 1) ? fBh[q].w : fBh[q].y;
                    mma16816(acc[i][j], fAh[i], b0, b1);
                }
            }
        }
    }

    if (RELU) {
#pragma unroll
        for (int i = 0; i < 4; i++)
#pragma unroll
            for (int j = 0; j < 4; j++)
#pragma unroll
                for (int r = 0; r < 4; r++) acc[i][j][r] = fmaxf(acc[i][j][r], 0.f);
    }

    if (MODE == 0) {
        float* Cb = C + (size_t)bz * sCf;
        const int row0 = by * 128 + wm * 64 + (lane >> 2);
        const int colb = bx * 128 + wn * 32 + (lane & 3) * 2;
#pragma unroll
        for (int i = 0; i < 4; i++)
#pragma unroll
            for (int j = 0; j < 4; j++) {
                int r = row0 + i * 16;
                int col = colb + j * 8;
                *reinterpret_cast<float2*>(Cb + (size_t)r * Ncols + col) =
                    make_float2(acc[i][j][0] * outScale, acc[i][j][1] * outScale);
                *reinterpret_cast<float2*>(Cb + (size_t)(r + 8) * Ncols + col) =
                    make_float2(acc[i][j][2] * outScale, acc[i][j][3] * outScale);
            }
    } else if (MODE == 1) {
        // emit A-frags (hi) for next GEMM (C-frag layout == A-frag layout)
        const int nkNext = Ncols >> 4;
        const size_t mb = (size_t)bz * mbPerBatch + by;
#pragma unroll
        for (int i = 0; i < 4; i++)
#pragma unroll
            for (int jp = 0; jp < 2; jp++) {
                float* a0 = acc[i][2 * jp];
                float* a1 = acc[i][2 * jp + 1];
                int kcg = bx * 8 + wn * 2 + jp;
                size_t di = (mb * nkNext + kcg) * 256 + (wm * 4 + i) * 32 + lane;
                FH[di] = make_uint4(pk(a0[0], a0[1]), pk(a0[2], a0[3]),
                                    pk(a1[0], a1[1]), pk(a1[2], a1[3]));
            }
    } else {
        // MODE 2: emit B-frags (hi) for next GEMM via smem transpose.
        CP_WAIT0();
        __syncthreads();
        float* sf = (float*)sm;  // 128 x 132 fp32
        const int r0 = wm * 64 + (lane >> 2);
        const int c0 = wn * 32 + (lane & 3) * 2;
#pragma unroll
        for (int i = 0; i < 4; i++)
#pragma unroll
            for (int j = 0; j < 4; j++) {
                int rr = r0 + i * 16, cc = c0 + j * 8;
                sf[rr * 132 + cc] = acc[i][j][0];
                sf[rr * 132 + cc + 1] = acc[i][j][1];
                sf[(rr + 8) * 132 + cc] = acc[i][j][2];
                sf[(rr + 8) * 132 + cc + 1] = acc[i][j][3];
            }
        __syncthreads();
        const int batchO = by >> 5;
        const int mbLoc = by & 31;
        const int jj = tid >> 5;
        const int ln = tid & 31;
        const int n0 = 16 * jj + (ln >> 2);
        const int k0b = (ln & 3) * 2;
#pragma unroll
        for (int kb = 0; kb < 8; kb++) {
            int k0 = kb * 16 + k0b;
            float e[8];
            e[0] = sf[k0 * 132 + n0];
            e[1] = sf[(k0 + 1) * 132 + n0];
            e[2] = sf[(k0 + 8) * 132 + n0];
            e[3] = sf[(k0 + 9) * 132 + n0];
            e[4] = sf[k0 * 132 + n0 + 8];
            e[5] = sf[(k0 + 1) * 132 + n0 + 8];
            e[6] = sf[(k0 + 8) * 132 + n0 + 8];
            e[7] = sf[(k0 + 9) * 132 + n0 + 8];
            int kc = mbLoc * 8 + kb;
            size_t di = (size_t)batchO * sFu4 + ((size_t)kc * nbX + bx) * 256 + tid;
            FH[di] = make_uint4(pk(e[0], e[1]), pk(e[2], e[3]),
                                pk(e[4], e[5]), pk(e[6], e[7]));
        }
    }
}

// ---------------------------------------------------------------------------
template <int MODE, int RELU>
static void launch_gemm(int M, int Ncols, int K,
                        const uint4* Ah, const uint4* Bh,
                        float* C, uint4* FH,
                        int batch, size_t sBu4, size_t sCf,
                        int mbPerBatch, size_t sFu4, float outScale) {
    int nbX = Ncols / 128;
    dim3 g(nbX * batch, M / 128);
    int smem = 81920;  // 5 x 16KB; MODE2 transpose (67584 B) fits
    cudaFuncSetAttribute(gemm_f16<MODE, RELU>,
                         cudaFuncAttributeMaxDynamicSharedMemorySize, smem);
    gemm_f16<MODE, RELU><<<g, 256, smem>>>(
        Ah, Bh, C, FH, Ncols, K, nbX, sBu4, sCf, mbPerBatch, sFu4, outScale);
}

extern "C" void kernel_launch(void* const* d_in, const int* in_sizes, int n_in,
                              void* d_out, int out_size) {
    const float* x   = (const float*)d_in[0];  // [B, N, 256]
    const float* adj = (const float*)d_in[1];
    const float* S   = (const float*)d_in[2];
    const float* W1  = (const float*)d_in[3];  // [256, 512]
    const float* W2  = (const float*)d_in[4];  // [512, 1024]
    const float* W3  = (const float*)d_in[5];  // [1024, 256]
    float* out = (float*)d_out;                // [B, N, 256]

    uint4 *AwH, *FaH, *FbH, *WH;
    cudaGetSymbolAddress((void**)&AwH, g_AwH);
    cudaGetSymbolAddress((void**)&FaH, g_FaH);
    cudaGetSymbolAddress((void**)&FbH, g_FbH);
    cudaGetSymbolAddress((void**)&WH, g_WH);

    const size_t sX  = (size_t)NN * 256 / 8;   // per-batch u4 strides
    const size_t sH1 = (size_t)NN * 512 / 8;
    const size_t sS3 = (size_t)NN * 256 / 8;

    // One fused prep launch: Aw, x, W1, W2, W3.
    prep_all<<<3296, 256>>>(adj, S, x, W1, W2, W3, AwH, FbH, WH);

    // G1: t1 = Aw @ x -> A-frags (Fa).
    launch_gemm<1, 0>(NN, 256, NN, AwH, FbH, nullptr, FaH,
                      BB, sX, 0, NN / 128, 0, 1.0f);
    // G2: h1 = relu(t1 @ W1) -> B-frags (Fb).
    launch_gemm<2, 1>(BB * NN, 512, 256, FaH, WH, nullptr, FbH,
                      1, 0, 0, 0, sH1, 1.0f);
    // G3: t2 = Aw @ h1 -> A-frags (Fa).
    launch_gemm<1, 0>(NN, 512, NN, AwH, FbH, nullptr, FaH,
                      BB, sH1, 0, NN / 128, 0, 1.0f);
    // G4: h2 = relu(t2 @ W2) -> A-frags (Fb).
    launch_gemm<1, 1>(BB * NN, 1024, 512, FaH, WH + 16384, nullptr, FbH,
                      1, 0, 0, 0, 0, 1.0f);
    // G5: s3 = h2 @ W3 -> B-frags (Fa).
    launch_gemm<2, 0>(BB * NN, 256, 1024, FbH, WH + 81920, nullptr, FaH,
                      1, 0, 0, 0, sS3, 1.0f);
    // G6: out = 64 * (Aw @ s3) -> fp32.
    launch_gemm<0, 0>(NN, 256, NN, AwH, FaH, out, nullptr,
                      BB, sS3, (size_t)NN * 256, 0, 0, OSCALE);
}

// round 15
// speedup vs baseline: 1.4951x; 1.0181x over previous
#include <cuda_runtime.h>
#include <cuda_fp16.h>
#include <cstdint>

// GCN — reassociated 3-layer GCN, fp16 hi-only mma.sync, globally scaled.
// x' = x/64; out *= 64 (relu positively homogeneous).
// G1: t1=Aw@x   G2: h1=relu(t1@W1)   G3: t2=Aw@h1
// G4: h2=relu(t2@W2)   G5: s3=h2@W3   G6: out=64*Aw@s3
// All 1-product fp16-hi; fp32 accum. 6-stage cp.async, 2 chunks per sync.

#define NN 4096
#define BB 4
#define XSCALE (1.0f / 64.0f)
#define OSCALE 64.0f

// Fragment-tiled storage: A blocks 128m x 16k = 256 uint4 (block = mb*nkc+kc),
// B blocks 16k x 128n = 256 uint4 (block = kc*nnb+nb).
__device__ uint4 g_AwH[(size_t)NN * NN / 8];
__device__ uint4 g_FaH[(size_t)BB * NN * 1024 / 8];  // ping
__device__ uint4 g_FbH[(size_t)BB * NN * 1024 / 8];  // pong
__device__ uint4 g_WH[114688];  // W1@0, W2@16384, W3@81920

// ---------------------------------------------------------------------------
__device__ __forceinline__ uint32_t smem_u32(const void* p) {
    uint32_t a;
    asm("{ .reg .u64 t; cvta.to.shared.u64 t, %1; cvt.u32.u64 %0, t; }"
        : "=r"(a) : "l"(p));
    return a;
}
__device__ __forceinline__ uint32_t pk(float a, float b) {
    __half2 t = __floats2half2_rn(a, b);
    return *reinterpret_cast<uint32_t*>(&t);
}
__device__ __forceinline__ void cpa16(uint32_t saddr, const void* gaddr) {
    asm volatile("cp.async.cg.shared.global [%0], [%1], 16;"
                 :: "r"(saddr), "l"(gaddr));
}
#define CP_COMMIT() asm volatile("cp.async.commit_group;" ::: "memory")
#define CP_WAIT2()  asm volatile("cp.async.wait_group 2;" ::: "memory")
#define CP_WAIT0()  asm volatile("cp.async.wait_group 0;" ::: "memory")

__device__ __forceinline__ void mma16816(float* c, const uint4& a,
                                         uint32_t b0, uint32_t b1) {
    asm volatile(
        "mma.sync.aligned.m16n8k16.row.col.f32.f16.f16.f32 "
        "{%0,%1,%2,%3},{%4,%5,%6,%7},{%8,%9},{%0,%1,%2,%3};"
        : "+f"(c[0]), "+f"(c[1]), "+f"(c[2]), "+f"(c[3])
        : "r"(a.x), "r"(a.y), "r"(a.z), "r"(a.w), "r"(b0), "r"(b1));
}

// ---------------------------------------------------------------------------
// Prep bodies (shared-memory staged, coalesced float4 reads).
// ---------------------------------------------------------------------------
__device__ __forceinline__ void prep_A_body(const float* __restrict__ src,
                                            const float* __restrict__ mul,
                                            uint4* __restrict__ dhi,
                                            int K, int kcb, int mb,
                                            float* smraw) {
    float (*smt)[68] = (float (*)[68])smraw;
    const int tid = threadIdx.x;
    const int colBase = kcb * 64;
    const size_t rowBase = (size_t)mb * 128;

    const int c4 = tid & 15;
    const int r0 = tid >> 4;
#pragma unroll
    for (int i = 0; i < 8; i++) {
        int r = r0 + i * 16;
        const float4 v = ((const float4*)(src + (rowBase + r) * K + colBase))[c4];
        const float4 s = ((const float4*)(mul + (rowBase + r) * K + colBase))[c4];
        *(float4*)&smt[r][c4 * 4] =
            make_float4(v.x * s.x, v.y * s.y, v.z * s.z, v.w * s.w);
    }
    __syncthreads();

    const int lane = tid & 31;
    const int mt = tid >> 5;
    const int rr = mt * 16 + (lane >> 2);
    const int cb = (lane & 3) * 2;
    const int nkc = K >> 4;
#pragma unroll
    for (int kb = 0; kb < 4; kb++) {
        int c0 = kb * 16 + cb;
        uint4 H = make_uint4(
            pk(smt[rr][c0],     smt[rr][c0 + 1]),
            pk(smt[rr + 8][c0], smt[rr + 8][c0 + 1]),
            pk(smt[rr][c0 + 8], smt[rr][c0 + 9]),
            pk(smt[rr + 8][c0 + 8], smt[rr + 8][c0 + 9]));
        dhi[((size_t)mb * nkc + (size_t)(kcb * 4 + kb)) * 256 + tid] = H;
    }
}

__device__ __forceinline__ void prep_B_body(const float* __restrict__ src,
                                            uint4* __restrict__ dhi,
                                            int Ncols, int nb, int kcb,
                                            float scale, float* smraw) {
    float (*smt)[132] = (float (*)[132])smraw;
    const int tid = threadIdx.x;
    const int c4 = tid & 31;
    const int r0 = tid >> 5;
#pragma unroll
    for (int i = 0; i < 4; i++) {
        int r = r0 + i * 8;
        float4 v = ((const float4*)(src + (size_t)(kcb * 32 + r) * Ncols +
                                    nb * 128))[c4];
        v.x *= scale; v.y *= scale; v.z *= scale; v.w *= scale;
        *(float4*)&smt[r][c4 * 4] = v;
    }
    __syncthreads();

    const int lane = tid & 31;
    const int j = tid >> 5;
    const int n0 = j * 16 + (lane >> 2);
    const int k0b = (lane & 3) * 2;
    const int nnb = Ncols >> 7;
#pragma unroll
    for (int kk = 0; kk < 2; kk++) {
        int k0 = kk * 16 + k0b;
        float e[8];
        e[0] = smt[k0][n0];     e[1] = smt[k0 + 1][n0];
        e[2] = smt[k0 + 8][n0]; e[3] = smt[k0 + 9][n0];
        e[4] = smt[k0][n0 + 8];     e[5] = smt[k0 + 1][n0 + 8];
        e[6] = smt[k0 + 8][n0 + 8]; e[7] = smt[k0 + 9][n0 + 8];
        size_t blk = (size_t)(kcb * 2 + kk) * nnb + nb;
        dhi[blk * 256 + tid] = make_uint4(pk(e[0], e[1]), pk(e[2], e[3]),
                                          pk(e[4], e[5]), pk(e[6], e[7]));
    }
}

// ---------------------------------------------------------------------------
// Fused prep: ONE launch does Aw, x, W1, W2, W3.
//   [0,2048):    Aw [4096,4096] .* S   (kcb = r&63, mb = r>>6)
//   [2048,3072): x  [4096,256] x4 batch (per batch 256: nb=r&1, kcb=r>>1)
//   [3072,3104): W1 [256,512]   (nb=r&3, kcb=r>>2)
//   [3104,3232): W2 [512,1024]  (nb=r&7, kcb=r>>3)
//   [3232,3296): W3 [1024,256]  (nb=r&1, kcb=r>>1)
// ---------------------------------------------------------------------------
__global__ __launch_bounds__(256)
void prep_all(const float* __restrict__ adj, const float* __restrict__ S,
              const float* __restrict__ x, const float* __restrict__ W1,
              const float* __restrict__ W2, const float* __restrict__ W3,
              uint4* __restrict__ AwH, uint4* __restrict__ FbH,
              uint4* __restrict__ WH) {
    __shared__ float smraw[128 * 68];
    const int bid = blockIdx.x;
    if (bid < 2048) {
        prep_A_body(adj, S, AwH, NN, bid & 63, bid >> 6, smraw);
    } else if (bid < 3072) {
        int r = bid - 2048;
        int bz = r >> 8;
        r &= 255;
        prep_B_body(x + (size_t)bz * NN * 256,
                    FbH + (size_t)bz * (NN * 256 / 8),
                    256, r & 1, r >> 1, XSCALE, smraw);
    } else if (bid < 3104) {
        int r = bid - 3072;
        prep_B_body(W1, WH, 512, r & 3, r >> 2, 1.0f, smraw);
    } else if (bid < 3232) {
        int r = bid - 3104;
        prep_B_body(W2, WH + 16384, 1024, r & 7, r >> 3, 1.0f, smraw);
    } else {
        int r = bid - 3232;
        prep_B_body(W3, WH + 81920, 256, r & 1, r >> 1, 1.0f, smraw);
    }
}

// ---------------------------------------------------------------------------
// GEMM: BM=128, BN=128, BK=32, 6-stage cp.async (16KB/stage), 8 warps (2x4),
// warp tile 64x32, 1 product. 2 chunks per sync (one barrier per 64-K).
// MODE 0: fp32 store (scaled).  MODE 1: emit A-frags (hi).
// MODE 2: emit B-frags (hi, smem transpose).  RELU before emission.
// grid: x = nbX*batch (bx = x%nbX, bz = x/nbX), y = M/128.
// Requires K % 64 == 0 (all K here: 256, 512, 1024, 4096).
// ---------------------------------------------------------------------------
template <int MODE, int RELU>
__global__ __launch_bounds__(256, 2)
void gemm_f16(const uint4* __restrict__ Ah, const uint4* __restrict__ Bh,
              float* __restrict__ C, uint4* __restrict__ FH,
              int Ncols, int K, int nbX,
              size_t sBu4, size_t sCf, int mbPerBatch, size_t sFu4,
              float outScale) {
    extern __shared__ __align__(128) char sm[];
    const int tid = threadIdx.x;
    const int lane = tid & 31;
    const int wid = tid >> 5;
    const int wm = wid >> 2;
    const int wn = wid & 3;
    const int bx = blockIdx.x % nbX;
    const int bz = blockIdx.x / nbX;
    const int by = blockIdx.y;

    const int nc2 = K >> 5;        // 32-k chunks (even)
    const int nkc = K >> 4;
    const int nnb = Ncols >> 7;

    // Pointer-stride issue state
    const uint32_t saBase = smem_u32(sm) + tid * 16;
    const uint4* Ap = Ah + (size_t)by * nkc * 256 + tid;
    const uint4* Bp = Bh + (size_t)bz * sBu4 + (size_t)bx * 256 + tid;
    const size_t bHalf = (size_t)nnb * 256;
    const size_t bStep = bHalf * 2;

    float acc[4][4][4];
#pragma unroll
    for (int i = 0; i < 4; i++)
#pragma unroll
        for (int j = 0; j < 4; j++)
#pragma unroll
            for (int r = 0; r < 4; r++) acc[i][j][r] = 0.f;

    auto issue = [&](int s) {
        uint32_t sa = saBase + s * 16384;
        cpa16(sa,         Ap);
        cpa16(sa + 4096,  Ap + 256);
        cpa16(sa + 8192,  Bp);
        cpa16(sa + 12288, Bp + bHalf);
        Ap += 512;
        Bp += bStep;
        CP_COMMIT();
    };

    issue(0); issue(1); issue(2); issue(3);

    int sload = 4;   // next stage slot to fill (mod 6)
    int scomp = 0;   // stage being computed (mod 6)
    for (int c = 0; c < nc2; c += 2) {
        CP_WAIT2();          // chunks c, c+1 landed (<=2 groups outstanding)
        __syncthreads();
        if (c + 4 < nc2) { issue(sload); if (++sload == 6) sload = 0; }
        if (c + 5 < nc2) { issue(sload); if (++sload == 6) sload = 0; }

#pragma unroll
        for (int h = 0; h < 2; h++) {
            const char* st = sm + scomp * 16384;
            if (++scomp == 6) scomp = 0;
#pragma unroll
            for (int kk = 0; kk < 2; ++kk) {
                const uint4* sAh = (const uint4*)(st + kk * 4096);
                const uint4* sBh = (const uint4*)(st + 8192 + kk * 4096);
                uint4 fAh[4], fBh[2];
#pragma unroll
                for (int i = 0; i < 4; i++)
                    fAh[i] = sAh[(wm * 4 + i) * 32 + lane];
#pragma unroll
                for (int q = 0; q < 2; q++)
                    fBh[q] = sBh[(wn * 2 + q) * 32 + lane];
#pragma unroll
                for (int i = 0; i < 4; i++) {
#pragma unroll
                    for (int j = 0; j < 4; j++) {
                        int q = j >> 1;
                        uint32_t b0 = (j & 1) ? fBh[q].z : fBh[q].x;
                        uint32_t b1 = (j & 1) ? fBh[q].w : fBh[q].y;
                        mma16816(acc[i][j], fAh[i], b0, b1);
                    }
                }
            }
        }
    }

    if (RELU) {
#pragma unroll
        for (int i = 0; i < 4; i++)
#pragma unroll
            for (int j = 0; j < 4; j++)
#pragma unroll
                for (int r = 0; r < 4; r++) acc[i][j][r] = fmaxf(acc[i][j][r], 0.f);
    }

    if (MODE == 0) {
        float* Cb = C + (size_t)bz * sCf;
        const int row0 = by * 128 + wm * 64 + (lane >> 2);
        const int colb = bx * 128 + wn * 32 + (lane & 3) * 2;
#pragma unroll
        for (int i = 0; i < 4; i++)
#pragma unroll
            for (int j = 0; j < 4; j++) {
                int r = row0 + i * 16;
                int col = colb + j * 8;
                *reinterpret_cast<float2*>(Cb + (size_t)r * Ncols + col) =
                    make_float2(acc[i][j][0] * outScale, acc[i][j][1] * outScale);
                *reinterpret_cast<float2*>(Cb + (size_t)(r + 8) * Ncols + col) =
                    make_float2(acc[i][j][2] * outScale, acc[i][j][3] * outScale);
            }
    } else if (MODE == 1) {
        // emit A-frags (hi) for next GEMM (C-frag layout == A-frag layout)
        const int nkNext = Ncols >> 4;
        const size_t mb = (size_t)bz * mbPerBatch + by;
#pragma unroll
        for (int i = 0; i < 4; i++)
#pragma unroll
            for (int jp = 0; jp < 2; jp++) {
                float* a0 = acc[i][2 * jp];
                float* a1 = acc[i][2 * jp + 1];
                int kcg = bx * 8 + wn * 2 + jp;
                size_t di = (mb * nkNext + kcg) * 256 + (wm * 4 + i) * 32 + lane;
                FH[di] = make_uint4(pk(a0[0], a0[1]), pk(a0[2], a0[3]),
                                    pk(a1[0], a1[1]), pk(a1[2], a1[3]));
            }
    } else {
        // MODE 2: emit B-frags (hi) for next GEMM via smem transpose.
        CP_WAIT0();
        __syncthreads();
        float* sf = (float*)sm;  // 128 x 132 fp32
        const int r0 = wm * 64 + (lane >> 2);
        const int c0 = wn * 32 + (lane & 3) * 2;
#pragma unroll
        for (int i = 0; i < 4; i++)
#pragma unroll
            for (int j = 0; j < 4; j++) {
                int rr = r0 + i * 16, cc = c0 + j * 8;
                sf[rr * 132 + cc] = acc[i][j][0];
                sf[rr * 132 + cc + 1] = acc[i][j][1];
                sf[(rr + 8) * 132 + cc] = acc[i][j][2];
                sf[(rr + 8) * 132 + cc + 1] = acc[i][j][3];
            }
        __syncthreads();
        const int batchO = by >> 5;
        const int mbLoc = by & 31;
        const int jj = tid >> 5;
        const int ln = tid & 31;
        const int n0 = 16 * jj + (ln >> 2);
        const int k0b = (ln & 3) * 2;
#pragma unroll
        for (int kb = 0; kb < 8; kb++) {
            int k0 = kb * 16 + k0b;
            float e[8];
            e[0] = sf[k0 * 132 + n0];
            e[1] = sf[(k0 + 1) * 132 + n0];
            e[2] = sf[(k0 + 8) * 132 + n0];
            e[3] = sf[(k0 + 9) * 132 + n0];
            e[4] = sf[k0 * 132 + n0 + 8];
            e[5] = sf[(k0 + 1) * 132 + n0 + 8];
            e[6] = sf[(k0 + 8) * 132 + n0 + 8];
            e[7] = sf[(k0 + 9) * 132 + n0 + 8];
            int kc = mbLoc * 8 + kb;
            size_t di = (size_t)batchO * sFu4 + ((size_t)kc * nbX + bx) * 256 + tid;
            FH[di] = make_uint4(pk(e[0], e[1]), pk(e[2], e[3]),
                                pk(e[4], e[5]), pk(e[6], e[7]));
        }
    }
}

// ---------------------------------------------------------------------------
template <int MODE, int RELU>
static void launch_gemm(int M, int Ncols, int K,
                        const uint4* Ah, const uint4* Bh,
                        float* C, uint4* FH,
                        int batch, size_t sBu4, size_t sCf,
                        int mbPerBatch, size_t sFu4, float outScale) {
    int nbX = Ncols / 128;
    dim3 g(nbX * batch, M / 128);
    int smem = 98304;  // 6 x 16KB; MODE2 transpose (67584 B) fits
    cudaFuncSetAttribute(gemm_f16<MODE, RELU>,
                         cudaFuncAttributeMaxDynamicSharedMemorySize, smem);
    gemm_f16<MODE, RELU><<<g, 256, smem>>>(
        Ah, Bh, C, FH, Ncols, K, nbX, sBu4, sCf, mbPerBatch, sFu4, outScale);
}

extern "C" void kernel_launch(void* const* d_in, const int* in_sizes, int n_in,
                              void* d_out, int out_size) {
    const float* x   = (const float*)d_in[0];  // [B, N, 256]
    const float* adj = (const float*)d_in[1];
    const float* S   = (const float*)d_in[2];
    const float* W1  = (const float*)d_in[3];  // [256, 512]
    const float* W2  = (const float*)d_in[4];  // [512, 1024]
    const float* W3  = (const float*)d_in[5];  // [1024, 256]
    float* out = (float*)d_out;                // [B, N, 256]

    uint4 *AwH, *FaH, *FbH, *WH;
    cudaGetSymbolAddress((void**)&AwH, g_AwH);
    cudaGetSymbolAddress((void**)&FaH, g_FaH);
    cudaGetSymbolAddress((void**)&FbH, g_FbH);
    cudaGetSymbolAddress((void**)&WH, g_WH);

    const size_t sX  = (size_t)NN * 256 / 8;   // per-batch u4 strides
    const size_t sH1 = (size_t)NN * 512 / 8;
    const size_t sS3 = (size_t)NN * 256 / 8;

    // One fused prep launch: Aw, x, W1, W2, W3.
    prep_all<<<3296, 256>>>(adj, S, x, W1, W2, W3, AwH, FbH, WH);

    // G1: t1 = Aw @ x -> A-frags (Fa).
    launch_gemm<1, 0>(NN, 256, NN, AwH, FbH, nullptr, FaH,
                      BB, sX, 0, NN / 128, 0, 1.0f);
    // G2: h1 = relu(t1 @ W1) -> B-frags (Fb).
    launch_gemm<2, 1>(BB * NN, 512, 256, FaH, WH, nullptr, FbH,
                      1, 0, 0, 0, sH1, 1.0f);
    // G3: t2 = Aw @ h1 -> A-frags (Fa).
    launch_gemm<1, 0>(NN, 512, NN, AwH, FbH, nullptr, FaH,
                      BB, sH1, 0, NN / 128, 0, 1.0f);
    // G4: h2 = relu(t2 @ W2) -> A-frags (Fb).
    launch_gemm<1, 1>(BB * NN, 1024, 512, FaH, WH + 16384, nullptr, FbH,
                      1, 0, 0, 0, 0, 1.0f);
    // G5: s3 = h2 @ W3 -> B-frags (Fa).
    launch_gemm<2, 0>(BB * NN, 256, 1024, FbH, WH + 81920, nullptr, FaH,
                      1, 0, 0, 0, sS3, 1.0f);
    // G6: out = 64 * (Aw @ s3) -> fp32.
    launch_gemm<0, 0>(NN, 256, NN, AwH, FaH, out, nullptr,
                      BB, sS3, (size_t)NN * 256, 0, 0, OSCALE);
}